// round 1
// baseline (speedup 1.0000x reference)
#include <cuda_runtime.h>
#include <math.h>
#include <float.h>

// ---------------- problem constants ----------------
constexpr int B_  = 8;
constexpr int T_  = 256;
constexpr int C_  = 1024;
constexpr int QD_ = 768;
constexpr int LQ_ = 24;
constexpr int K_  = 4;
constexpr int CC_ = 4;     // W/K
constexpr int NW_ = 241;   // T - W + 1
constexpr int S_  = 8;
constexpr int H_  = 4;
constexpr int HD_ = 256;   // C/H
constexpr int SL_ = NW_ * K_;  // 964

// ---------------- scratch (static device globals; no allocations) ----------------
__device__ float g_pv [B_*T_*C_];          // PE'd vis feats
__device__ float g_pq [B_*LQ_*QD_];        // PE'd query feats
__device__ float g_v  [B_*T_*C_];          // v after w_v1 proj
__device__ float g_e1 [B_*LQ_*C_];
__device__ float g_e2 [B_*LQ_*C_];
__device__ int   g_lab[B_*T_];
__device__ int   g_mod[B_*NW_*K_];
__device__ float g_avg[B_*SL_*C_];
__device__ float g_qq [B_*SL_*C_];         // pooled (attn q/v source)
__device__ float g_kk [B_*SL_*C_];         // gathered mod keys
__device__ float g_Q  [B_*SL_*C_];
__device__ float g_K  [B_*SL_*C_];
__device__ float g_V  [B_*SL_*C_];
__device__ float g_sc [(long)B_*H_*SL_*SL_]; // attention scores (~119MB)
__device__ float g_ao [B_*SL_*C_];         // attn output (pre out-proj)
__device__ float g_ob [B_*SL_*C_];         // out = attn @ w_out
__device__ float g_h  [B_*NW_*C_];         // mlp hidden
__device__ float g_fl [B_*C_*S_];          // flat pooled features

// ---------------- positional encoding add ----------------
__global__ void pe_add_kernel(const float* __restrict__ x, float* __restrict__ y,
                              int L, int d) {
    int row = blockIdx.x;            // b*L + l
    int l = row % L;
    const float* xr = x + (long)row * d;
    float* yr = y + (long)row * d;
    float pos = (float)l;
    float c0 = logf(10000.0f) / (float)d;
    for (int c = threadIdx.x; c < d; c += blockDim.x) {
        int i = c >> 1;
        float freq = expf(-(float)(2 * i) * c0);
        float ang = pos * freq;
        float pe = (c & 1) ? cosf(ang) : sinf(ang);
        yr[c] = xr[c] + pe;
    }
}

// ---------------- sim = v . e1^T, fused argmax over LQ ----------------
__global__ void sim_argmax_kernel(const float* __restrict__ v,
                                  const float* __restrict__ e1,
                                  int* __restrict__ labels) {
    int bt = blockIdx.x;             // b*T + t
    int b = bt / T_;
    __shared__ float sv[C_];
    __shared__ float svals[LQ_];
    const float* vr = v + (long)bt * C_;
    for (int c = threadIdx.x; c < C_; c += 256) sv[c] = vr[c];
    __syncthreads();
    int warp = threadIdx.x >> 5, lane = threadIdx.x & 31;
    for (int l = warp; l < LQ_; l += 8) {
        const float* er = e1 + ((long)b * LQ_ + l) * C_;
        float s = 0.f;
        for (int c = lane; c < C_; c += 32) s += sv[c] * er[c];
        #pragma unroll
        for (int o = 16; o; o >>= 1) s += __shfl_xor_sync(0xffffffffu, s, o);
        if (lane == 0) svals[l] = s;
    }
    __syncthreads();
    if (threadIdx.x == 0) {
        float best = svals[0]; int bi = 0;
        for (int l = 1; l < LQ_; l++)
            if (svals[l] > best) { best = svals[l]; bi = l; }
        labels[bt] = bi;
    }
}

// ---------------- majority vote (mode) per chunk ----------------
__global__ void mode_kernel(const int* __restrict__ labels, int* __restrict__ mode) {
    int idx = blockIdx.x * blockDim.x + threadIdx.x;
    if (idx >= B_ * NW_ * K_) return;
    int k = idx % K_;
    int nw = (idx / K_) % NW_;
    int b = idx / (K_ * NW_);
    int la[CC_];
    #pragma unroll
    for (int cc = 0; cc < CC_; cc++) la[cc] = labels[b * T_ + nw + k * CC_ + cc];
    int bestLab = 0x7fffffff, bestCnt = 0;
    #pragma unroll
    for (int cc = 0; cc < CC_; cc++) {
        int v = la[cc], cnt = 0;
        #pragma unroll
        for (int j = 0; j < CC_; j++) cnt += (la[j] == v) ? 1 : 0;
        if (cnt > bestCnt || (cnt == bestCnt && v < bestLab)) { bestCnt = cnt; bestLab = v; }
    }
    mode[idx] = bestLab;
}

// ---------------- window chunk mean over CC rows ----------------
__global__ void avg_kernel(const float* __restrict__ v, float* __restrict__ avg) {
    int s = blockIdx.x % SL_;
    int b = blockIdx.x / SL_;
    int nw = s / K_, k = s % K_;
    const float* base = v + ((long)b * T_ + nw + k * CC_) * C_;
    float* o = avg + ((long)b * SL_ + s) * C_;
    for (int c = threadIdx.x; c < C_; c += 256)
        o[c] = 0.25f * (base[c] + base[C_ + c] + base[2 * C_ + c] + base[3 * C_ + c]);
}

// ---------------- gather e2 rows by mode ----------------
__global__ void gather_kernel(const float* __restrict__ e2, const int* __restrict__ mode,
                              float* __restrict__ kk) {
    int s = blockIdx.x % SL_;
    int b = blockIdx.x / SL_;
    int m = mode[b * NW_ * K_ + s];
    const float* src = e2 + ((long)b * LQ_ + m) * C_;
    float* dst = kk + ((long)b * SL_ + s) * C_;
    for (int c = threadIdx.x; c < C_; c += 256) dst[c] = src[c];
}

// ---------------- generic tiled GEMM ----------------
// C = scale * (A @ op(B)) [+ bias] [relu]
// BT=true: B is (N,Kd) row-major (x @ W^T). BT=false: B is (Kd,N) row-major.
// Batch z: zo=z/zdiv, zi=z%zdiv; ptr += zo*s?o + zi*s?i.
template<bool BT, bool RELU>
__global__ void gemm_kernel(
    const float* __restrict__ A, int lda,
    const float* __restrict__ Bm, int ldb,
    float* __restrict__ Cm, int ldc,
    int M, int N, int Kd,
    const float* __restrict__ bias, float scale,
    long sAo, long sAi, long sBo, long sBi, long sCo, long sCi, int zdiv)
{
    constexpr int BMt = 128, BNt = 128, BKt = 16;
    int z = blockIdx.z;
    int zo = z / zdiv, zi = z - zo * zdiv;
    A  += zo * sAo + zi * sAi;
    Bm += zo * sBo + zi * sBi;
    Cm += zo * sCo + zi * sCi;

    __shared__ float As[BKt][BMt + 4];
    __shared__ float Bs[BKt][BNt + 4];

    int tid = threadIdx.x;
    int tx = tid & 15, ty = tid >> 4;
    int rowBase = blockIdx.y * BMt;
    int colBase = blockIdx.x * BNt;

    float acc[8][8];
    #pragma unroll
    for (int i = 0; i < 8; i++)
        #pragma unroll
        for (int j = 0; j < 8; j++) acc[i][j] = 0.f;

    for (int k0 = 0; k0 < Kd; k0 += BKt) {
        #pragma unroll
        for (int i = 0; i < 8; i++) {
            int idx = i * 256 + tid;
            int r = idx >> 4, kk = idx & 15;
            int gr = rowBase + r, gk = k0 + kk;
            As[kk][r] = (gr < M && gk < Kd) ? A[(long)gr * lda + gk] : 0.f;
        }
        if constexpr (BT) {
            #pragma unroll
            for (int i = 0; i < 8; i++) {
                int idx = i * 256 + tid;
                int c = idx >> 4, kk = idx & 15;
                int gc = colBase + c, gk = k0 + kk;
                Bs[kk][c] = (gc < N && gk < Kd) ? Bm[(long)gc * ldb + gk] : 0.f;
            }
        } else {
            #pragma unroll
            for (int i = 0; i < 8; i++) {
                int idx = i * 256 + tid;
                int kk = idx >> 7, c = idx & 127;
                int gc = colBase + c, gk = k0 + kk;
                Bs[kk][c] = (gc < N && gk < Kd) ? Bm[(long)gk * ldb + gc] : 0.f;
            }
        }
        __syncthreads();
        #pragma unroll
        for (int kk = 0; kk < BKt; kk++) {
            float a[8], bb[8];
            #pragma unroll
            for (int i = 0; i < 8; i++) a[i] = As[kk][ty * 8 + i];
            #pragma unroll
            for (int j = 0; j < 8; j++) bb[j] = Bs[kk][tx * 8 + j];
            #pragma unroll
            for (int i = 0; i < 8; i++)
                #pragma unroll
                for (int j = 0; j < 8; j++) acc[i][j] = fmaf(a[i], bb[j], acc[i][j]);
        }
        __syncthreads();
    }
    #pragma unroll
    for (int i = 0; i < 8; i++) {
        int r = rowBase + ty * 8 + i;
        if (r >= M) continue;
        #pragma unroll
        for (int j = 0; j < 8; j++) {
            int c = colBase + tx * 8 + j;
            if (c >= N) continue;
            float vv = acc[i][j] * scale;
            if (bias) vv += bias[c];
            if (RELU) vv = fmaxf(vv, 0.f);
            Cm[(long)r * ldc + c] = vv;
        }
    }
}

// ---------------- row softmax over SL ----------------
__global__ void softmax_kernel(float* __restrict__ sc) {
    long row = blockIdx.x;
    float* r = sc + row * SL_;
    __shared__ float red[256];
    float m = -FLT_MAX;
    for (int i = threadIdx.x; i < SL_; i += 256) m = fmaxf(m, r[i]);
    red[threadIdx.x] = m; __syncthreads();
    for (int o = 128; o; o >>= 1) {
        if (threadIdx.x < o) red[threadIdx.x] = fmaxf(red[threadIdx.x], red[threadIdx.x + o]);
        __syncthreads();
    }
    m = red[0]; __syncthreads();
    float sum = 0.f;
    for (int i = threadIdx.x; i < SL_; i += 256) { float e = __expf(r[i] - m); r[i] = e; sum += e; }
    red[threadIdx.x] = sum; __syncthreads();
    for (int o = 128; o; o >>= 1) {
        if (threadIdx.x < o) red[threadIdx.x] += red[threadIdx.x + o];
        __syncthreads();
    }
    float inv = 1.0f / red[0];
    for (int i = threadIdx.x; i < SL_; i += 256) r[i] *= inv;
}

// ---------------- pred head: (B,NW,C) @ w_p2^T -> d_out[b,j,nw] ----------------
__global__ void pred_kernel(const float* __restrict__ h, const float* __restrict__ w_p2,
                            const float* __restrict__ b_p2, float* __restrict__ out) {
    int bn = blockIdx.x;
    int b = bn / NW_, nw = bn % NW_;
    const float* hr = h + (long)bn * C_;
    __shared__ float r0[256], r1[256];
    float s0 = 0.f, s1 = 0.f;
    for (int c = threadIdx.x; c < C_; c += 256) {
        float x = hr[c];
        s0 += x * w_p2[c];
        s1 += x * w_p2[C_ + c];
    }
    r0[threadIdx.x] = s0; r1[threadIdx.x] = s1; __syncthreads();
    for (int o = 128; o; o >>= 1) {
        if (threadIdx.x < o) { r0[threadIdx.x] += r0[threadIdx.x + o]; r1[threadIdx.x] += r1[threadIdx.x + o]; }
        __syncthreads();
    }
    if (threadIdx.x == 0) {
        out[((long)b * 2 + 0) * NW_ + nw] = r0[0] + b_p2[0];
        out[((long)b * 2 + 1) * NW_ + nw] = r1[0] + b_p2[1];
    }
}

// ---------------- segment max-pool -> flat[b, c*S+s] ----------------
__global__ void maxpool_kernel(const float* __restrict__ ob, const int* __restrict__ vid_len,
                               float* __restrict__ flat) {
    int bs = blockIdx.x;
    int b = bs / S_, s = bs % S_;
    int Lb = vid_len[b] * K_;
    int start = (s * Lb) / S_;
    int end = ((s + 1) * Lb + S_ - 1) / S_;
    if (end > SL_) end = SL_;
    const float* base = ob + (long)b * SL_ * C_;
    for (int c = threadIdx.x; c < C_; c += 256) {
        float m = -FLT_MAX;
        for (int t = start; t < end; t++) m = fmaxf(m, base[(long)t * C_ + c]);
        flat[(long)b * C_ * S_ + c * S_ + s] = m;
    }
}

// ---------------- st/en heads ----------------
__global__ void head_kernel(const float* __restrict__ flat,
                            const float* __restrict__ w_st, const float* __restrict__ b_st,
                            const float* __restrict__ w_en, const float* __restrict__ b_en,
                            float* __restrict__ dout) {
    int id = blockIdx.x;                 // [0, B*S*2)
    int which = id & 1;
    int s = (id >> 1) % S_;
    int b = id / (2 * S_);
    const float* w = which ? w_en : w_st;
    const float* bias = which ? b_en : b_st;
    const float* f = flat + (long)b * C_ * S_;
    const float* wr = w + (long)s * C_ * S_;
    __shared__ float red[256];
    float sum = 0.f;
    for (int i = threadIdx.x; i < C_ * S_; i += 256) sum += f[i] * wr[i];
    red[threadIdx.x] = sum; __syncthreads();
    for (int o = 128; o; o >>= 1) {
        if (threadIdx.x < o) red[threadIdx.x] += red[threadIdx.x + o];
        __syncthreads();
    }
    if (threadIdx.x == 0)
        dout[B_ * 2 * NW_ + which * B_ * S_ + b * S_ + s] = red[0] + bias[s];
}

// ---------------- host-side GEMM dispatch ----------------
static void gemm(bool bt, bool relu,
                 const float* A, int lda, const float* Bm, int ldb,
                 float* Cm, int ldc, int M, int N, int Kd,
                 const float* bias, float scale,
                 long sAo, long sAi, long sBo, long sBi, long sCo, long sCi,
                 int zdiv, int zcount) {
    dim3 grid((N + 127) / 128, (M + 127) / 128, zcount);
    if (bt) {
        if (relu) gemm_kernel<true, true><<<grid, 256>>>(A, lda, Bm, ldb, Cm, ldc, M, N, Kd, bias, scale, sAo, sAi, sBo, sBi, sCo, sCi, zdiv);
        else      gemm_kernel<true, false><<<grid, 256>>>(A, lda, Bm, ldb, Cm, ldc, M, N, Kd, bias, scale, sAo, sAi, sBo, sBi, sCo, sCi, zdiv);
    } else {
        if (relu) gemm_kernel<false, true><<<grid, 256>>>(A, lda, Bm, ldb, Cm, ldc, M, N, Kd, bias, scale, sAo, sAi, sBo, sBi, sCo, sCi, zdiv);
        else      gemm_kernel<false, false><<<grid, 256>>>(A, lda, Bm, ldb, Cm, ldc, M, N, Kd, bias, scale, sAo, sAi, sBo, sBi, sCo, sCi, zdiv);
    }
}

extern "C" void kernel_launch(void* const* d_in, const int* in_sizes, int n_in,
                              void* d_out, int out_size) {
    (void)in_sizes; (void)n_in; (void)out_size;
    const float* vis   = (const float*)d_in[0];
    const float* qf    = (const float*)d_in[1];
    const int*   vlen  = (const int*)  d_in[2];
    const float* w_v1  = (const float*)d_in[3];  const float* b_v1 = (const float*)d_in[4];
    const float* w_v2  = (const float*)d_in[5];  const float* b_v2 = (const float*)d_in[6];
    const float* w_s1  = (const float*)d_in[7];  const float* b_s1 = (const float*)d_in[8];
    const float* w_s2  = (const float*)d_in[9];  const float* b_s2 = (const float*)d_in[10];
    const float* w_in  = (const float*)d_in[11]; const float* b_in = (const float*)d_in[12];
    const float* w_out = (const float*)d_in[13]; const float* b_out= (const float*)d_in[14];
    const float* w_p1  = (const float*)d_in[15]; const float* b_p1 = (const float*)d_in[16];
    const float* w_p2  = (const float*)d_in[17]; const float* b_p2 = (const float*)d_in[18];
    const float* w_st  = (const float*)d_in[19]; const float* b_st = (const float*)d_in[20];
    const float* w_en  = (const float*)d_in[21]; const float* b_en = (const float*)d_in[22];
    float* out = (float*)d_out;

    float *pv, *pq, *v, *e1, *e2, *avg, *qq, *kk, *Qm, *Km, *Vm, *sc, *ao, *ob, *hb, *fl;
    int *lab, *mod;
    cudaGetSymbolAddress((void**)&pv, g_pv);
    cudaGetSymbolAddress((void**)&pq, g_pq);
    cudaGetSymbolAddress((void**)&v,  g_v);
    cudaGetSymbolAddress((void**)&e1, g_e1);
    cudaGetSymbolAddress((void**)&e2, g_e2);
    cudaGetSymbolAddress((void**)&lab, g_lab);
    cudaGetSymbolAddress((void**)&mod, g_mod);
    cudaGetSymbolAddress((void**)&avg, g_avg);
    cudaGetSymbolAddress((void**)&qq, g_qq);
    cudaGetSymbolAddress((void**)&kk, g_kk);
    cudaGetSymbolAddress((void**)&Qm, g_Q);
    cudaGetSymbolAddress((void**)&Km, g_K);
    cudaGetSymbolAddress((void**)&Vm, g_V);
    cudaGetSymbolAddress((void**)&sc, g_sc);
    cudaGetSymbolAddress((void**)&ao, g_ao);
    cudaGetSymbolAddress((void**)&ob, g_ob);
    cudaGetSymbolAddress((void**)&hb, g_h);
    cudaGetSymbolAddress((void**)&fl, g_fl);

    // 1. positional encodings
    pe_add_kernel<<<B_ * T_, 256>>>(vis, pv, T_, C_);
    pe_add_kernel<<<B_ * LQ_, 256>>>(qf, pq, LQ_, QD_);

    // 2. v = pe(vis) @ w_v1^T + b_v1   (2048 x 1024 x 1024)
    gemm(true, false, pv, C_, w_v1, C_, v, C_, B_ * T_, C_, C_, b_v1, 1.f,
         0, 0, 0, 0, 0, 0, 1, 1);

    // 3. e1/e2 = pe(q) @ w_s{1,2}^T   (192 x 1024 x 768)
    gemm(true, false, pq, QD_, w_s1, QD_, e1, C_, B_ * LQ_, C_, QD_, b_s1, 1.f,
         0, 0, 0, 0, 0, 0, 1, 1);
    gemm(true, false, pq, QD_, w_s2, QD_, e2, C_, B_ * LQ_, C_, QD_, b_s2, 1.f,
         0, 0, 0, 0, 0, 0, 1, 1);

    // 4. labels = argmax_l v . e1
    sim_argmax_kernel<<<B_ * T_, 256>>>(v, e1, lab);

    // 5. mode per chunk; window means
    mode_kernel<<<(B_ * NW_ * K_ + 255) / 256, 256>>>(lab, mod);
    avg_kernel<<<B_ * SL_, 256>>>(v, avg);

    // 6. qq = avg @ w_v2^T + b_v2     (7712 x 1024 x 1024)
    gemm(true, false, avg, C_, w_v2, C_, qq, C_, B_ * SL_, C_, C_, b_v2, 1.f,
         0, 0, 0, 0, 0, 0, 1, 1);

    // 7. kk = e2[mode]
    gather_kernel<<<B_ * SL_, 256>>>(e2, mod, kk);

    // 8. QKV projections (w_in split rows: q, k, v)
    gemm(true, false, qq, C_, w_in,                 C_, Qm, C_, B_ * SL_, C_, C_, b_in,            1.f, 0,0,0,0,0,0, 1, 1);
    gemm(true, false, kk, C_, w_in + (long)C_ * C_, C_, Km, C_, B_ * SL_, C_, C_, b_in + C_,       1.f, 0,0,0,0,0,0, 1, 1);
    gemm(true, false, qq, C_, w_in + 2L * C_ * C_,  C_, Vm, C_, B_ * SL_, C_, C_, b_in + 2 * C_,   1.f, 0,0,0,0,0,0, 1, 1);

    // 9. scores = Q K^T / sqrt(HD), batched over (b,h); head = column slice of C
    gemm(true, false, Qm, C_, Km, C_, sc, SL_, SL_, SL_, HD_, nullptr, 0.0625f,
         (long)SL_ * C_, HD_, (long)SL_ * C_, HD_, (long)H_ * SL_ * SL_, (long)SL_ * SL_, H_, B_ * H_);

    // 10. softmax rows
    softmax_kernel<<<B_ * H_ * SL_, 256>>>(sc);

    // 11. attn @ V  (NN gemm), batched over (b,h)
    gemm(false, false, sc, SL_, Vm, C_, ao, C_, SL_, HD_, SL_, nullptr, 1.f,
         (long)H_ * SL_ * SL_, (long)SL_ * SL_, (long)SL_ * C_, HD_, (long)SL_ * C_, HD_, H_, B_ * H_);

    // 12. out projection
    gemm(true, false, ao, C_, w_out, C_, ob, C_, B_ * SL_, C_, C_, b_out, 1.f,
         0, 0, 0, 0, 0, 0, 1, 1);

    // 13. mlp: h = relu(out.reshape(B,NW,4096) @ w_p1^T + b_p1)  (1928 x 1024 x 4096)
    gemm(true, true, ob, K_ * C_, w_p1, K_ * C_, hb, C_, B_ * NW_, C_, K_ * C_, b_p1, 1.f,
         0, 0, 0, 0, 0, 0, 1, 1);

    // 14. pred head -> d_out[0 .. B*2*NW)
    pred_kernel<<<B_ * NW_, 256>>>(hb, w_p2, b_p2, out);

    // 15. segment max pool + st/en heads -> d_out tail
    maxpool_kernel<<<B_ * S_, 256>>>(ob, vlen, fl);
    head_kernel<<<B_ * S_ * 2, 256>>>(fl, w_st, b_st, w_en, b_en, out);
}

// round 3
// speedup vs baseline: 2.7969x; 2.7969x over previous
#include <cuda_runtime.h>
#include <math.h>
#include <float.h>
#include <stdint.h>

// ---------------- problem constants ----------------
constexpr int B_  = 8;
constexpr int T_  = 256;
constexpr int C_  = 1024;
constexpr int QD_ = 768;
constexpr int LQ_ = 24;
constexpr int K_  = 4;
constexpr int CC_ = 4;     // W/K
constexpr int NW_ = 241;   // T - W + 1
constexpr int S_  = 8;
constexpr int H_  = 4;
constexpr int HD_ = 256;   // C/H
constexpr int SL_ = NW_ * K_;  // 964

// ---------------- scratch (static device globals; no allocations) ----------------
__device__ float g_pv [B_*T_*C_];
__device__ float g_pq [B_*LQ_*QD_];
__device__ float g_v  [B_*T_*C_];
__device__ float g_e1 [B_*LQ_*C_];
__device__ float g_e2 [B_*LQ_*C_];
__device__ int   g_lab[B_*T_];
__device__ int   g_mod[B_*NW_*K_];
__device__ float g_avg[B_*SL_*C_];
__device__ float g_qq [B_*SL_*C_];
__device__ float g_kk [B_*SL_*C_];
__device__ float g_Q  [B_*SL_*C_];
__device__ float g_K  [B_*SL_*C_];
__device__ float g_V  [B_*SL_*C_];
__device__ float g_sc [(long)B_*H_*SL_*SL_];
__device__ float g_ao [B_*SL_*C_];
__device__ float g_ob [B_*SL_*C_];
__device__ float g_h  [B_*NW_*C_];
__device__ float g_fl [B_*C_*S_];

// ---------------- positional encoding add ----------------
__global__ void pe_add_kernel(const float* __restrict__ x, float* __restrict__ y,
                              int L, int d) {
    int row = blockIdx.x;
    int l = row % L;
    const float* xr = x + (long)row * d;
    float* yr = y + (long)row * d;
    float pos = (float)l;
    float c0 = logf(10000.0f) / (float)d;
    for (int c = threadIdx.x; c < d; c += blockDim.x) {
        int i = c >> 1;
        float freq = expf(-(float)(2 * i) * c0);
        float ang = pos * freq;
        float pe = (c & 1) ? cosf(ang) : sinf(ang);
        yr[c] = xr[c] + pe;
    }
}

// ---------------- sim = v . e1^T, fused argmax over LQ ----------------
__global__ void sim_argmax_kernel(const float* __restrict__ v,
                                  const float* __restrict__ e1,
                                  int* __restrict__ labels) {
    int bt = blockIdx.x;
    int b = bt / T_;
    __shared__ float sv[C_];
    __shared__ float svals[LQ_];
    const float* vr = v + (long)bt * C_;
    for (int c = threadIdx.x; c < C_; c += 256) sv[c] = vr[c];
    __syncthreads();
    int warp = threadIdx.x >> 5, lane = threadIdx.x & 31;
    for (int l = warp; l < LQ_; l += 8) {
        const float* er = e1 + ((long)b * LQ_ + l) * C_;
        float s = 0.f;
        for (int c = lane; c < C_; c += 32) s += sv[c] * er[c];
        #pragma unroll
        for (int o = 16; o; o >>= 1) s += __shfl_xor_sync(0xffffffffu, s, o);
        if (lane == 0) svals[l] = s;
    }
    __syncthreads();
    if (threadIdx.x == 0) {
        float best = svals[0]; int bi = 0;
        for (int l = 1; l < LQ_; l++)
            if (svals[l] > best) { best = svals[l]; bi = l; }
        labels[bt] = bi;
    }
}

// ---------------- majority vote (mode) per chunk ----------------
__global__ void mode_kernel(const int* __restrict__ labels, int* __restrict__ mode) {
    int idx = blockIdx.x * blockDim.x + threadIdx.x;
    if (idx >= B_ * NW_ * K_) return;
    int k = idx % K_;
    int nw = (idx / K_) % NW_;
    int b = idx / (K_ * NW_);
    int la[CC_];
    #pragma unroll
    for (int cc = 0; cc < CC_; cc++) la[cc] = labels[b * T_ + nw + k * CC_ + cc];
    int bestLab = 0x7fffffff, bestCnt = 0;
    #pragma unroll
    for (int cc = 0; cc < CC_; cc++) {
        int v = la[cc], cnt = 0;
        #pragma unroll
        for (int j = 0; j < CC_; j++) cnt += (la[j] == v) ? 1 : 0;
        if (cnt > bestCnt || (cnt == bestCnt && v < bestLab)) { bestCnt = cnt; bestLab = v; }
    }
    mode[idx] = bestLab;
}

// ---------------- window chunk mean over CC rows ----------------
__global__ void avg_kernel(const float* __restrict__ v, float* __restrict__ avg) {
    int s = blockIdx.x % SL_;
    int b = blockIdx.x / SL_;
    int nw = s / K_, k = s % K_;
    const float* base = v + ((long)b * T_ + nw + k * CC_) * C_;
    float* o = avg + ((long)b * SL_ + s) * C_;
    for (int c = threadIdx.x; c < C_; c += 256)
        o[c] = 0.25f * (base[c] + base[C_ + c] + base[2 * C_ + c] + base[3 * C_ + c]);
}

// ---------------- gather e2 rows by mode ----------------
__global__ void gather_kernel(const float* __restrict__ e2, const int* __restrict__ mode,
                              float* __restrict__ kk) {
    int s = blockIdx.x % SL_;
    int b = blockIdx.x / SL_;
    int m = mode[b * NW_ * K_ + s];
    const float* src = e2 + ((long)b * LQ_ + m) * C_;
    float* dst = kk + ((long)b * SL_ + s) * C_;
    for (int c = threadIdx.x; c < C_; c += 256) dst[c] = src[c];
}

// ---------------- fp32 tiled GEMM (kept for precision-critical small GEMMs) ----------------
template<bool BT, bool RELU>
__global__ void gemm_kernel(
    const float* __restrict__ A, int lda,
    const float* __restrict__ Bm, int ldb,
    float* __restrict__ Cm, int ldc,
    int M, int N, int Kd,
    const float* __restrict__ bias, float scale,
    long sAo, long sAi, long sBo, long sBi, long sCo, long sCi, int zdiv)
{
    constexpr int BMt = 128, BNt = 128, BKt = 16;
    int z = blockIdx.z;
    int zo = z / zdiv, zi = z - zo * zdiv;
    A  += zo * sAo + zi * sAi;
    Bm += zo * sBo + zi * sBi;
    Cm += zo * sCo + zi * sCi;

    __shared__ float As[BKt][BMt + 4];
    __shared__ float Bs[BKt][BNt + 4];

    int tid = threadIdx.x;
    int tx = tid & 15, ty = tid >> 4;
    int rowBase = blockIdx.y * BMt;
    int colBase = blockIdx.x * BNt;

    float acc[8][8];
    #pragma unroll
    for (int i = 0; i < 8; i++)
        #pragma unroll
        for (int j = 0; j < 8; j++) acc[i][j] = 0.f;

    for (int k0 = 0; k0 < Kd; k0 += BKt) {
        #pragma unroll
        for (int i = 0; i < 8; i++) {
            int idx = i * 256 + tid;
            int r = idx >> 4, kk = idx & 15;
            int gr = rowBase + r, gk = k0 + kk;
            As[kk][r] = (gr < M && gk < Kd) ? A[(long)gr * lda + gk] : 0.f;
        }
        if constexpr (BT) {
            #pragma unroll
            for (int i = 0; i < 8; i++) {
                int idx = i * 256 + tid;
                int c = idx >> 4, kk = idx & 15;
                int gc = colBase + c, gk = k0 + kk;
                Bs[kk][c] = (gc < N && gk < Kd) ? Bm[(long)gc * ldb + gk] : 0.f;
            }
        } else {
            #pragma unroll
            for (int i = 0; i < 8; i++) {
                int idx = i * 256 + tid;
                int kk = idx >> 7, c = idx & 127;
                int gc = colBase + c, gk = k0 + kk;
                Bs[kk][c] = (gc < N && gk < Kd) ? Bm[(long)gk * ldb + gc] : 0.f;
            }
        }
        __syncthreads();
        #pragma unroll
        for (int kk = 0; kk < BKt; kk++) {
            float a[8], bb[8];
            #pragma unroll
            for (int i = 0; i < 8; i++) a[i] = As[kk][ty * 8 + i];
            #pragma unroll
            for (int j = 0; j < 8; j++) bb[j] = Bs[kk][tx * 8 + j];
            #pragma unroll
            for (int i = 0; i < 8; i++)
                #pragma unroll
                for (int j = 0; j < 8; j++) acc[i][j] = fmaf(a[i], bb[j], acc[i][j]);
        }
        __syncthreads();
    }
    #pragma unroll
    for (int i = 0; i < 8; i++) {
        int r = rowBase + ty * 8 + i;
        if (r >= M) continue;
        #pragma unroll
        for (int j = 0; j < 8; j++) {
            int c = colBase + tx * 8 + j;
            if (c >= N) continue;
            float vv = acc[i][j] * scale;
            if (bias) vv += bias[c];
            if (RELU) vv = fmaxf(vv, 0.f);
            Cm[(long)r * ldc + c] = vv;
        }
    }
}

// ================= tf32 tensor-core GEMM =================
// C = scale * (A @ op(B)) [+bias][relu]
// BT=true:  B is (N,Kd) row-major (x @ W^T style).
// BT=false: B is (Kd,N) row-major.
// 128x128 CTA tile, BK=16, cp.async double buffer, 8 warps at 64x32 warp tiles,
// mma.sync.m16n8k8 tf32 with cvt.rna fragment rounding.

__device__ __forceinline__ uint32_t f2tf32(float x) {
    uint32_t u;
    asm("cvt.rna.tf32.f32 %0, %1;" : "=r"(u) : "f"(x));
    return u;
}
__device__ __forceinline__ void cp_async16(uint32_t saddr, const void* gptr, int srcBytes) {
    asm volatile("cp.async.cg.shared.global [%0], [%1], 16, %2;\n"
                 :: "r"(saddr), "l"(gptr), "r"(srcBytes));
}
__device__ __forceinline__ void cp_commit() {
    asm volatile("cp.async.commit_group;\n");
}
template<int N>
__device__ __forceinline__ void cp_wait() {
    asm volatile("cp.async.wait_group %0;\n" :: "n"(N));
}
__device__ __forceinline__ void mma_tf32(float& d0, float& d1, float& d2, float& d3,
                                         uint32_t a0, uint32_t a1, uint32_t a2, uint32_t a3,
                                         uint32_t b0, uint32_t b1) {
    asm volatile("mma.sync.aligned.m16n8k8.row.col.f32.tf32.tf32.f32 "
                 "{%0,%1,%2,%3}, {%4,%5,%6,%7}, {%8,%9}, {%0,%1,%2,%3};\n"
                 : "+f"(d0), "+f"(d1), "+f"(d2), "+f"(d3)
                 : "r"(a0), "r"(a1), "r"(a2), "r"(a3), "r"(b0), "r"(b1));
}

template<bool BT, bool RELU>
__global__ __launch_bounds__(256) void gemm_tf32_kernel(
    const float* __restrict__ A, int lda,
    const float* __restrict__ Bm, int ldb,
    float* __restrict__ Cm, int ldc,
    int M, int N, int Kd,
    const float* __restrict__ bias, float scale,
    long sAo, long sAi, long sBo, long sBi, long sCo, long sCi, int zdiv)
{
    constexpr int BK = 16;
    constexpr int APAD = 20;                       // A row stride (floats)
    constexpr int BSTRIDE = BT ? 20 : 132;         // BT: [n][k] stride 20; NN: [k][n] stride 132
    constexpr int BSZ = BT ? 128 * 20 : BK * 132;

    __shared__ float As[2][128][APAD];
    __shared__ float Bs[2][BSZ];

    int z = blockIdx.z;
    int zo = z / zdiv, zi = z - zo * zdiv;
    A  += zo * sAo + zi * sAi;
    Bm += zo * sBo + zi * sBi;
    Cm += zo * sCo + zi * sCi;

    int tid = threadIdx.x;
    int wid = tid >> 5, lane = tid & 31;
    int g = lane >> 2, t = lane & 3;
    int warpM = (wid >> 2) * 64;   // 2 warps in M
    int warpN = (wid & 3) * 32;    // 4 warps in N
    int rowBase = blockIdx.y * 128;
    int colBase = blockIdx.x * 128;

    float acc[4][4][4];
    #pragma unroll
    for (int i = 0; i < 4; i++)
        #pragma unroll
        for (int j = 0; j < 4; j++)
            #pragma unroll
            for (int q = 0; q < 4; q++) acc[i][j][q] = 0.f;

    int KT = (Kd + BK - 1) / BK;

    auto load_stage = [&](int kt, int s) {
        int k0 = kt * BK;
        // A: 128x16 floats = 512 vec4; 2 per thread
        #pragma unroll
        for (int i = 0; i < 2; i++) {
            int v = i * 256 + tid;
            int r = v >> 2, kv = (v & 3) * 4;
            int gr = rowBase + r, gk = k0 + kv;
            bool ok = (gr < M) && (gk < Kd);
            long gro = ok ? (long)gr : 0;
            long gko = ok ? (long)gk : 0;
            uint32_t sa = (uint32_t)__cvta_generic_to_shared(&As[s][r][kv]);
            cp_async16(sa, A + gro * lda + gko, ok ? 16 : 0);
        }
        // B: 512 vec4; 2 per thread
        #pragma unroll
        for (int i = 0; i < 2; i++) {
            int v = i * 256 + tid;
            if constexpr (BT) {
                int n = v >> 2, kv = (v & 3) * 4;
                int gn = colBase + n, gk = k0 + kv;
                bool ok = (gn < N) && (gk < Kd);
                long gno = ok ? (long)gn : 0;
                long gko = ok ? (long)gk : 0;
                uint32_t sa = (uint32_t)__cvta_generic_to_shared(&Bs[s][n * BSTRIDE + kv]);
                cp_async16(sa, Bm + gno * ldb + gko, ok ? 16 : 0);
            } else {
                int kk = v >> 5, nv = (v & 31) * 4;
                int gk = k0 + kk, gn = colBase + nv;
                bool ok = (gk < Kd) && (gn < N);
                long gko = ok ? (long)gk : 0;
                long gno = ok ? (long)gn : 0;
                uint32_t sa = (uint32_t)__cvta_generic_to_shared(&Bs[s][kk * BSTRIDE + nv]);
                cp_async16(sa, Bm + gko * ldb + gno, ok ? 16 : 0);
            }
        }
    };

    load_stage(0, 0);
    cp_commit();

    for (int kt = 0; kt < KT; kt++) {
        int s = kt & 1;
        if (kt + 1 < KT) load_stage(kt + 1, (kt + 1) & 1);
        cp_commit();
        cp_wait<1>();
        __syncthreads();

        #pragma unroll
        for (int ks = 0; ks < 2; ks++) {
            int k8 = ks * 8;
            uint32_t af[4][4], bf[4][2];
            #pragma unroll
            for (int i = 0; i < 4; i++) {
                int r0 = warpM + i * 16 + g;
                af[i][0] = f2tf32(As[s][r0][k8 + t]);
                af[i][1] = f2tf32(As[s][r0 + 8][k8 + t]);
                af[i][2] = f2tf32(As[s][r0][k8 + 4 + t]);
                af[i][3] = f2tf32(As[s][r0 + 8][k8 + 4 + t]);
            }
            #pragma unroll
            for (int j = 0; j < 4; j++) {
                int n0 = warpN + j * 8 + g;
                if constexpr (BT) {
                    bf[j][0] = f2tf32(Bs[s][n0 * BSTRIDE + k8 + t]);
                    bf[j][1] = f2tf32(Bs[s][n0 * BSTRIDE + k8 + 4 + t]);
                } else {
                    bf[j][0] = f2tf32(Bs[s][(k8 + t) * BSTRIDE + n0]);
                    bf[j][1] = f2tf32(Bs[s][(k8 + 4 + t) * BSTRIDE + n0]);
                }
            }
            #pragma unroll
            for (int i = 0; i < 4; i++)
                #pragma unroll
                for (int j = 0; j < 4; j++)
                    mma_tf32(acc[i][j][0], acc[i][j][1], acc[i][j][2], acc[i][j][3],
                             af[i][0], af[i][1], af[i][2], af[i][3],
                             bf[j][0], bf[j][1]);
        }
        __syncthreads();
    }

    // epilogue
    #pragma unroll
    for (int i = 0; i < 4; i++) {
        int r0 = rowBase + warpM + i * 16 + g;
        int r1 = r0 + 8;
        #pragma unroll
        for (int j = 0; j < 4; j++) {
            int c0 = colBase + warpN + j * 8 + t * 2;
            float b0v = 0.f, b1v = 0.f;
            if (bias && c0 < N)     b0v = bias[c0];
            if (bias && c0 + 1 < N) b1v = bias[c0 + 1];
            if (r0 < M) {
                if (c0 < N) {
                    float vv = acc[i][j][0] * scale + b0v;
                    if (RELU) vv = fmaxf(vv, 0.f);
                    Cm[(long)r0 * ldc + c0] = vv;
                }
                if (c0 + 1 < N) {
                    float vv = acc[i][j][1] * scale + b1v;
                    if (RELU) vv = fmaxf(vv, 0.f);
                    Cm[(long)r0 * ldc + c0 + 1] = vv;
                }
            }
            if (r1 < M) {
                if (c0 < N) {
                    float vv = acc[i][j][2] * scale + b0v;
                    if (RELU) vv = fmaxf(vv, 0.f);
                    Cm[(long)r1 * ldc + c0] = vv;
                }
                if (c0 + 1 < N) {
                    float vv = acc[i][j][3] * scale + b1v;
                    if (RELU) vv = fmaxf(vv, 0.f);
                    Cm[(long)r1 * ldc + c0 + 1] = vv;
                }
            }
        }
    }
}

// ---------------- row softmax over SL ----------------
__global__ void softmax_kernel(float* __restrict__ sc) {
    long row = blockIdx.x;
    float* r = sc + row * SL_;
    __shared__ float red[256];
    float m = -FLT_MAX;
    for (int i = threadIdx.x; i < SL_; i += 256) m = fmaxf(m, r[i]);
    red[threadIdx.x] = m; __syncthreads();
    for (int o = 128; o; o >>= 1) {
        if (threadIdx.x < o) red[threadIdx.x] = fmaxf(red[threadIdx.x], red[threadIdx.x + o]);
        __syncthreads();
    }
    m = red[0]; __syncthreads();
    float sum = 0.f;
    for (int i = threadIdx.x; i < SL_; i += 256) { float e = __expf(r[i] - m); r[i] = e; sum += e; }
    red[threadIdx.x] = sum; __syncthreads();
    for (int o = 128; o; o >>= 1) {
        if (threadIdx.x < o) red[threadIdx.x] += red[threadIdx.x + o];
        __syncthreads();
    }
    float inv = 1.0f / red[0];
    for (int i = threadIdx.x; i < SL_; i += 256) r[i] *= inv;
}

// ---------------- pred head ----------------
__global__ void pred_kernel(const float* __restrict__ h, const float* __restrict__ w_p2,
                            const float* __restrict__ b_p2, float* __restrict__ out) {
    int bn = blockIdx.x;
    int b = bn / NW_, nw = bn % NW_;
    const float* hr = h + (long)bn * C_;
    __shared__ float r0[256], r1[256];
    float s0 = 0.f, s1 = 0.f;
    for (int c = threadIdx.x; c < C_; c += 256) {
        float x = hr[c];
        s0 += x * w_p2[c];
        s1 += x * w_p2[C_ + c];
    }
    r0[threadIdx.x] = s0; r1[threadIdx.x] = s1; __syncthreads();
    for (int o = 128; o; o >>= 1) {
        if (threadIdx.x < o) { r0[threadIdx.x] += r0[threadIdx.x + o]; r1[threadIdx.x] += r1[threadIdx.x + o]; }
        __syncthreads();
    }
    if (threadIdx.x == 0) {
        out[((long)b * 2 + 0) * NW_ + nw] = r0[0] + b_p2[0];
        out[((long)b * 2 + 1) * NW_ + nw] = r1[0] + b_p2[1];
    }
}

// ---------------- segment max-pool ----------------
__global__ void maxpool_kernel(const float* __restrict__ ob, const int* __restrict__ vid_len,
                               float* __restrict__ flat) {
    int bs = blockIdx.x;
    int b = bs / S_, s = bs % S_;
    int Lb = vid_len[b] * K_;
    int start = (s * Lb) / S_;
    int end = ((s + 1) * Lb + S_ - 1) / S_;
    if (end > SL_) end = SL_;
    const float* base = ob + (long)b * SL_ * C_;
    for (int c = threadIdx.x; c < C_; c += 256) {
        float m = -FLT_MAX;
        for (int t = start; t < end; t++) m = fmaxf(m, base[(long)t * C_ + c]);
        flat[(long)b * C_ * S_ + c * S_ + s] = m;
    }
}

// ---------------- st/en heads ----------------
__global__ void head_kernel(const float* __restrict__ flat,
                            const float* __restrict__ w_st, const float* __restrict__ b_st,
                            const float* __restrict__ w_en, const float* __restrict__ b_en,
                            float* __restrict__ dout) {
    int id = blockIdx.x;
    int which = id & 1;
    int s = (id >> 1) % S_;
    int b = id / (2 * S_);
    const float* w = which ? w_en : w_st;
    const float* bias = which ? b_en : b_st;
    const float* f = flat + (long)b * C_ * S_;
    const float* wr = w + (long)s * C_ * S_;
    __shared__ float red[256];
    float sum = 0.f;
    for (int i = threadIdx.x; i < C_ * S_; i += 256) sum += f[i] * wr[i];
    red[threadIdx.x] = sum; __syncthreads();
    for (int o = 128; o; o >>= 1) {
        if (threadIdx.x < o) red[threadIdx.x] += red[threadIdx.x + o];
        __syncthreads();
    }
    if (threadIdx.x == 0)
        dout[B_ * 2 * NW_ + which * B_ * S_ + b * S_ + s] = red[0] + bias[s];
}

// ---------------- host-side dispatch ----------------
static void gemm_f32(bool bt, bool relu,
                     const float* A, int lda, const float* Bm, int ldb,
                     float* Cm, int ldc, int M, int N, int Kd,
                     const float* bias, float scale) {
    dim3 grid((N + 127) / 128, (M + 127) / 128, 1);
    if (bt) {
        if (relu) gemm_kernel<true, true><<<grid, 256>>>(A, lda, Bm, ldb, Cm, ldc, M, N, Kd, bias, scale, 0,0,0,0,0,0, 1);
        else      gemm_kernel<true, false><<<grid, 256>>>(A, lda, Bm, ldb, Cm, ldc, M, N, Kd, bias, scale, 0,0,0,0,0,0, 1);
    } else {
        if (relu) gemm_kernel<false, true><<<grid, 256>>>(A, lda, Bm, ldb, Cm, ldc, M, N, Kd, bias, scale, 0,0,0,0,0,0, 1);
        else      gemm_kernel<false, false><<<grid, 256>>>(A, lda, Bm, ldb, Cm, ldc, M, N, Kd, bias, scale, 0,0,0,0,0,0, 1);
    }
}

static void gemm_tf(bool bt, bool relu,
                    const float* A, int lda, const float* Bm, int ldb,
                    float* Cm, int ldc, int M, int N, int Kd,
                    const float* bias, float scale,
                    long sAo, long sAi, long sBo, long sBi, long sCo, long sCi,
                    int zdiv, int zcount) {
    dim3 grid((N + 127) / 128, (M + 127) / 128, zcount);
    if (bt) {
        if (relu) gemm_tf32_kernel<true, true><<<grid, 256>>>(A, lda, Bm, ldb, Cm, ldc, M, N, Kd, bias, scale, sAo, sAi, sBo, sBi, sCo, sCi, zdiv);
        else      gemm_tf32_kernel<true, false><<<grid, 256>>>(A, lda, Bm, ldb, Cm, ldc, M, N, Kd, bias, scale, sAo, sAi, sBo, sBi, sCo, sCi, zdiv);
    } else {
        if (relu) gemm_tf32_kernel<false, true><<<grid, 256>>>(A, lda, Bm, ldb, Cm, ldc, M, N, Kd, bias, scale, sAo, sAi, sBo, sBi, sCo, sCi, zdiv);
        else      gemm_tf32_kernel<false, false><<<grid, 256>>>(A, lda, Bm, ldb, Cm, ldc, M, N, Kd, bias, scale, sAo, sAi, sBo, sBi, sCo, sCi, zdiv);
    }
}

extern "C" void kernel_launch(void* const* d_in, const int* in_sizes, int n_in,
                              void* d_out, int out_size) {
    (void)in_sizes; (void)n_in; (void)out_size;
    const float* vis   = (const float*)d_in[0];
    const float* qf    = (const float*)d_in[1];
    const int*   vlen  = (const int*)  d_in[2];
    const float* w_v1  = (const float*)d_in[3];  const float* b_v1 = (const float*)d_in[4];
    const float* w_v2  = (const float*)d_in[5];  const float* b_v2 = (const float*)d_in[6];
    const float* w_s1  = (const float*)d_in[7];  const float* b_s1 = (const float*)d_in[8];
    const float* w_s2  = (const float*)d_in[9];  const float* b_s2 = (const float*)d_in[10];
    const float* w_in  = (const float*)d_in[11]; const float* b_in = (const float*)d_in[12];
    const float* w_out = (const float*)d_in[13]; const float* b_out= (const float*)d_in[14];
    const float* w_p1  = (const float*)d_in[15]; const float* b_p1 = (const float*)d_in[16];
    const float* w_p2  = (const float*)d_in[17]; const float* b_p2 = (const float*)d_in[18];
    const float* w_st  = (const float*)d_in[19]; const float* b_st = (const float*)d_in[20];
    const float* w_en  = (const float*)d_in[21]; const float* b_en = (const float*)d_in[22];
    float* out = (float*)d_out;

    float *pv, *pq, *v, *e1, *e2, *avg, *qq, *kk, *Qm, *Km, *Vm, *sc, *ao, *ob, *hb, *fl;
    int *lab, *mod;
    cudaGetSymbolAddress((void**)&pv, g_pv);
    cudaGetSymbolAddress((void**)&pq, g_pq);
    cudaGetSymbolAddress((void**)&v,  g_v);
    cudaGetSymbolAddress((void**)&e1, g_e1);
    cudaGetSymbolAddress((void**)&e2, g_e2);
    cudaGetSymbolAddress((void**)&lab, g_lab);
    cudaGetSymbolAddress((void**)&mod, g_mod);
    cudaGetSymbolAddress((void**)&avg, g_avg);
    cudaGetSymbolAddress((void**)&qq, g_qq);
    cudaGetSymbolAddress((void**)&kk, g_kk);
    cudaGetSymbolAddress((void**)&Qm, g_Q);
    cudaGetSymbolAddress((void**)&Km, g_K);
    cudaGetSymbolAddress((void**)&Vm, g_V);
    cudaGetSymbolAddress((void**)&sc, g_sc);
    cudaGetSymbolAddress((void**)&ao, g_ao);
    cudaGetSymbolAddress((void**)&ob, g_ob);
    cudaGetSymbolAddress((void**)&hb, g_h);
    cudaGetSymbolAddress((void**)&fl, g_fl);

    // 1. positional encodings
    pe_add_kernel<<<B_ * T_, 256>>>(vis, pv, T_, C_);
    pe_add_kernel<<<B_ * LQ_, 256>>>(qf, pq, LQ_, QD_);

    // 2. v = pe(vis) @ w_v1^T + b_v1  — fp32 (feeds argmax labels; precision-critical)
    gemm_f32(true, false, pv, C_, w_v1, C_, v, C_, B_ * T_, C_, C_, b_v1, 1.f);

    // 3. e1/e2 — fp32 (e1 feeds argmax)
    gemm_f32(true, false, pq, QD_, w_s1, QD_, e1, C_, B_ * LQ_, C_, QD_, b_s1, 1.f);
    gemm_f32(true, false, pq, QD_, w_s2, QD_, e2, C_, B_ * LQ_, C_, QD_, b_s2, 1.f);

    // 4-5. labels, mode, window means
    sim_argmax_kernel<<<B_ * T_, 256>>>(v, e1, lab);
    mode_kernel<<<(B_ * NW_ * K_ + 255) / 256, 256>>>(lab, mod);
    avg_kernel<<<B_ * SL_, 256>>>(v, avg);

    // 6. qq = avg @ w_v2^T + b_v2  (tf32)
    gemm_tf(true, false, avg, C_, w_v2, C_, qq, C_, B_ * SL_, C_, C_, b_v2, 1.f,
            0,0,0,0,0,0, 1, 1);

    // 7. kk = e2[mode]
    gather_kernel<<<B_ * SL_, 256>>>(e2, mod, kk);

    // 8. QKV projections (tf32)
    gemm_tf(true, false, qq, C_, w_in,                 C_, Qm, C_, B_ * SL_, C_, C_, b_in,          1.f, 0,0,0,0,0,0, 1, 1);
    gemm_tf(true, false, kk, C_, w_in + (long)C_ * C_, C_, Km, C_, B_ * SL_, C_, C_, b_in + C_,     1.f, 0,0,0,0,0,0, 1, 1);
    gemm_tf(true, false, qq, C_, w_in + 2L * C_ * C_,  C_, Vm, C_, B_ * SL_, C_, C_, b_in + 2 * C_, 1.f, 0,0,0,0,0,0, 1, 1);

    // 9. scores = Q K^T / sqrt(HD), batched over (b,h)  (tf32)
    gemm_tf(true, false, Qm, C_, Km, C_, sc, SL_, SL_, SL_, HD_, nullptr, 0.0625f,
            (long)SL_ * C_, HD_, (long)SL_ * C_, HD_, (long)H_ * SL_ * SL_, (long)SL_ * SL_, H_, B_ * H_);

    // 10. softmax
    softmax_kernel<<<B_ * H_ * SL_, 256>>>(sc);

    // 11. attn @ V (NN, tf32), batched over (b,h)
    gemm_tf(false, false, sc, SL_, Vm, C_, ao, C_, SL_, HD_, SL_, nullptr, 1.f,
            (long)H_ * SL_ * SL_, (long)SL_ * SL_, (long)SL_ * C_, HD_, (long)SL_ * C_, HD_, H_, B_ * H_);

    // 12. out projection (tf32)
    gemm_tf(true, false, ao, C_, w_out, C_, ob, C_, B_ * SL_, C_, C_, b_out, 1.f,
            0,0,0,0,0,0, 1, 1);

    // 13. mlp (tf32 + relu)
    gemm_tf(true, true, ob, K_ * C_, w_p1, K_ * C_, hb, C_, B_ * NW_, C_, K_ * C_, b_p1, 1.f,
            0,0,0,0,0,0, 1, 1);

    // 14-15. heads
    pred_kernel<<<B_ * NW_, 256>>>(hb, w_p2, b_p2, out);
    maxpool_kernel<<<B_ * S_, 256>>>(ob, vlen, fl);
    head_kernel<<<B_ * S_ * 2, 256>>>(fl, w_st, b_st, w_en, b_en, out);
}

// round 9
// speedup vs baseline: 3.1328x; 1.1201x over previous
#include <cuda_runtime.h>
#include <math.h>
#include <float.h>
#include <stdint.h>

// ---------------- problem constants ----------------
constexpr int B_  = 8;
constexpr int T_  = 256;
constexpr int C_  = 1024;
constexpr int QD_ = 768;
constexpr int LQ_ = 24;
constexpr int K_  = 4;
constexpr int CC_ = 4;     // W/K
constexpr int NW_ = 241;   // T - W + 1
constexpr int S_  = 8;
constexpr int H_  = 4;
constexpr int HD_ = 256;   // C/H
constexpr int SL_ = NW_ * K_;  // 964

// ---------------- scratch (static device globals; no allocations) ----------------
__device__ float g_pv [B_*T_*C_];
__device__ float g_pq [B_*LQ_*QD_];
__device__ float g_v  [B_*T_*C_];
__device__ float g_e1 [B_*LQ_*C_];
__device__ float g_e2 [B_*LQ_*C_];
__device__ int   g_lab[B_*T_];
__device__ int   g_mod[B_*NW_*K_];
__device__ float g_avg[B_*SL_*C_];
__device__ float g_qq [B_*SL_*C_];
__device__ float g_kk [B_*SL_*C_];
__device__ float g_Q  [B_*SL_*C_];
__device__ float g_K  [B_*SL_*C_];
__device__ float g_V  [B_*SL_*C_];
__device__ float g_sc [(long)B_*H_*SL_*SL_];
__device__ float g_ao [B_*SL_*C_];
__device__ float g_ob [B_*SL_*C_];
__device__ float g_h  [B_*NW_*C_];
__device__ float g_fl [B_*C_*S_];

// ---------------- positional encoding add ----------------
__global__ void pe_add_kernel(const float* __restrict__ x, float* __restrict__ y,
                              int L, int d) {
    int row = blockIdx.x;
    int l = row % L;
    const float* xr = x + (long)row * d;
    float* yr = y + (long)row * d;
    float pos = (float)l;
    float c0 = logf(10000.0f) / (float)d;
    for (int c = threadIdx.x; c < d; c += blockDim.x) {
        int i = c >> 1;
        float freq = expf(-(float)(2 * i) * c0);
        float ang = pos * freq;
        float pe = (c & 1) ? cosf(ang) : sinf(ang);
        yr[c] = xr[c] + pe;
    }
}

// ---------------- sim = v . e1^T, fused argmax over LQ ----------------
__global__ void sim_argmax_kernel(const float* __restrict__ v,
                                  const float* __restrict__ e1,
                                  int* __restrict__ labels) {
    int bt = blockIdx.x;
    int b = bt / T_;
    __shared__ float sv[C_];
    __shared__ float svals[LQ_];
    const float* vr = v + (long)bt * C_;
    for (int c = threadIdx.x; c < C_; c += 256) sv[c] = vr[c];
    __syncthreads();
    int warp = threadIdx.x >> 5, lane = threadIdx.x & 31;
    for (int l = warp; l < LQ_; l += 8) {
        const float* er = e1 + ((long)b * LQ_ + l) * C_;
        float s = 0.f;
        for (int c = lane; c < C_; c += 32) s += sv[c] * er[c];
        #pragma unroll
        for (int o = 16; o; o >>= 1) s += __shfl_xor_sync(0xffffffffu, s, o);
        if (lane == 0) svals[l] = s;
    }
    __syncthreads();
    if (threadIdx.x == 0) {
        float best = svals[0]; int bi = 0;
        for (int l = 1; l < LQ_; l++)
            if (svals[l] > best) { best = svals[l]; bi = l; }
        labels[bt] = bi;
    }
}

// ---------------- majority vote (mode) per chunk ----------------
__global__ void mode_kernel(const int* __restrict__ labels, int* __restrict__ mode) {
    int idx = blockIdx.x * blockDim.x + threadIdx.x;
    if (idx >= B_ * NW_ * K_) return;
    int k = idx % K_;
    int nw = (idx / K_) % NW_;
    int b = idx / (K_ * NW_);
    int la[CC_];
    #pragma unroll
    for (int cc = 0; cc < CC_; cc++) la[cc] = labels[b * T_ + nw + k * CC_ + cc];
    int bestLab = 0x7fffffff, bestCnt = 0;
    #pragma unroll
    for (int cc = 0; cc < CC_; cc++) {
        int v = la[cc], cnt = 0;
        #pragma unroll
        for (int j = 0; j < CC_; j++) cnt += (la[j] == v) ? 1 : 0;
        if (cnt > bestCnt || (cnt == bestCnt && v < bestLab)) { bestCnt = cnt; bestLab = v; }
    }
    mode[idx] = bestLab;
}

// ---------------- window chunk mean over CC rows ----------------
__global__ void avg_kernel(const float* __restrict__ v, float* __restrict__ avg) {
    int s = blockIdx.x % SL_;
    int b = blockIdx.x / SL_;
    int nw = s / K_, k = s % K_;
    const float* base = v + ((long)b * T_ + nw + k * CC_) * C_;
    float* o = avg + ((long)b * SL_ + s) * C_;
    for (int c = threadIdx.x; c < C_; c += 256)
        o[c] = 0.25f * (base[c] + base[C_ + c] + base[2 * C_ + c] + base[3 * C_ + c]);
}

// ---------------- gather e2 rows by mode ----------------
__global__ void gather_kernel(const float* __restrict__ e2, const int* __restrict__ mode,
                              float* __restrict__ kk) {
    int s = blockIdx.x % SL_;
    int b = blockIdx.x / SL_;
    int m = mode[b * NW_ * K_ + s];
    const float* src = e2 + ((long)b * LQ_ + m) * C_;
    float* dst = kk + ((long)b * SL_ + s) * C_;
    for (int c = threadIdx.x; c < C_; c += 256) dst[c] = src[c];
}

// ================= tf32 tensor-core GEMM =================
// C = scale * (A @ op(B)) [+bias][relu]
// BT=true:  B is (N,Kd) row-major (x @ W^T style).
// BT=false: B is (Kd,N) row-major.
// HILO=true: 3xTF32 error-compensated (near-fp32 accuracy: hi*hi + hi*lo + lo*hi).
// 128x128 CTA tile, BK=16, cp.async double buffer, 8 warps at 64x32 warp tiles.

__device__ __forceinline__ uint32_t f2tf32(float x) {
    uint32_t u;
    asm("cvt.rna.tf32.f32 %0, %1;" : "=r"(u) : "f"(x));
    return u;
}
__device__ __forceinline__ void split_tf32(float x, uint32_t& hi, uint32_t& lo) {
    asm("cvt.rna.tf32.f32 %0, %1;" : "=r"(hi) : "f"(x));
    float r = x - __uint_as_float(hi);
    asm("cvt.rna.tf32.f32 %0, %1;" : "=r"(lo) : "f"(r));
}
__device__ __forceinline__ void cp_async16(uint32_t saddr, const void* gptr, int srcBytes) {
    asm volatile("cp.async.cg.shared.global [%0], [%1], 16, %2;\n"
                 :: "r"(saddr), "l"(gptr), "r"(srcBytes));
}
__device__ __forceinline__ void cp_commit() {
    asm volatile("cp.async.commit_group;\n");
}
template<int N>
__device__ __forceinline__ void cp_wait() {
    asm volatile("cp.async.wait_group %0;\n" :: "n"(N));
}
__device__ __forceinline__ void mma_tf32(float& d0, float& d1, float& d2, float& d3,
                                         uint32_t a0, uint32_t a1, uint32_t a2, uint32_t a3,
                                         uint32_t b0, uint32_t b1) {
    asm volatile("mma.sync.aligned.m16n8k8.row.col.f32.tf32.tf32.f32 "
                 "{%0,%1,%2,%3}, {%4,%5,%6,%7}, {%8,%9}, {%0,%1,%2,%3};\n"
                 : "+f"(d0), "+f"(d1), "+f"(d2), "+f"(d3)
                 : "r"(a0), "r"(a1), "r"(a2), "r"(a3), "r"(b0), "r"(b1));
}

template<bool BT, bool RELU, bool HILO>
__global__ __launch_bounds__(256) void gemm_tf32_kernel(
    const float* __restrict__ A, int lda,
    const float* __restrict__ Bm, int ldb,
    float* __restrict__ Cm, int ldc,
    int M, int N, int Kd,
    const float* __restrict__ bias, float scale,
    long sAo, long sAi, long sBo, long sBi, long sCo, long sCi, int zdiv)
{
    constexpr int BK = 16;
    constexpr int APAD = 20;                       // A row stride (floats)
    constexpr int BSTRIDE = BT ? 20 : 132;         // BT: [n][k] stride 20; NN: [k][n] stride 132
    constexpr int BSZ = BT ? 128 * 20 : BK * 132;

    __shared__ float As[2][128][APAD];
    __shared__ float Bs[2][BSZ];

    int z = blockIdx.z;
    int zo = z / zdiv, zi = z - zo * zdiv;
    A  += zo * sAo + zi * sAi;
    Bm += zo * sBo + zi * sBi;
    Cm += zo * sCo + zi * sCi;

    int tid = threadIdx.x;
    int wid = tid >> 5, lane = tid & 31;
    int g = lane >> 2, t = lane & 3;
    int warpM = (wid >> 2) * 64;   // 2 warps in M
    int warpN = (wid & 3) * 32;    // 4 warps in N
    int rowBase = blockIdx.y * 128;
    int colBase = blockIdx.x * 128;

    float acc[4][4][4];
    #pragma unroll
    for (int i = 0; i < 4; i++)
        #pragma unroll
        for (int j = 0; j < 4; j++)
            #pragma unroll
            for (int q = 0; q < 4; q++) acc[i][j][q] = 0.f;

    int KT = (Kd + BK - 1) / BK;

    auto load_stage = [&](int kt, int s) {
        int k0 = kt * BK;
        #pragma unroll
        for (int i = 0; i < 2; i++) {
            int v = i * 256 + tid;
            int r = v >> 2, kv = (v & 3) * 4;
            int gr = rowBase + r, gk = k0 + kv;
            bool ok = (gr < M) && (gk < Kd);
            long gro = ok ? (long)gr : 0;
            long gko = ok ? (long)gk : 0;
            uint32_t sa = (uint32_t)__cvta_generic_to_shared(&As[s][r][kv]);
            cp_async16(sa, A + gro * lda + gko, ok ? 16 : 0);
        }
        #pragma unroll
        for (int i = 0; i < 2; i++) {
            int v = i * 256 + tid;
            if constexpr (BT) {
                int n = v >> 2, kv = (v & 3) * 4;
                int gn = colBase + n, gk = k0 + kv;
                bool ok = (gn < N) && (gk < Kd);
                long gno = ok ? (long)gn : 0;
                long gko = ok ? (long)gk : 0;
                uint32_t sa = (uint32_t)__cvta_generic_to_shared(&Bs[s][n * BSTRIDE + kv]);
                cp_async16(sa, Bm + gno * ldb + gko, ok ? 16 : 0);
            } else {
                int kk = v >> 5, nv = (v & 31) * 4;
                int gk = k0 + kk, gn = colBase + nv;
                bool ok = (gk < Kd) && (gn < N);
                long gko = ok ? (long)gk : 0;
                long gno = ok ? (long)gn : 0;
                uint32_t sa = (uint32_t)__cvta_generic_to_shared(&Bs[s][kk * BSTRIDE + nv]);
                cp_async16(sa, Bm + gko * ldb + gno, ok ? 16 : 0);
            }
        }
    };

    load_stage(0, 0);
    cp_commit();

    for (int kt = 0; kt < KT; kt++) {
        int s = kt & 1;
        if (kt + 1 < KT) load_stage(kt + 1, (kt + 1) & 1);
        cp_commit();
        cp_wait<1>();
        __syncthreads();

        #pragma unroll
        for (int ks = 0; ks < 2; ks++) {
            int k8 = ks * 8;
            uint32_t af[4][4], bf[4][2];
            uint32_t al[4][4], bl[4][2];
            #pragma unroll
            for (int i = 0; i < 4; i++) {
                int r0 = warpM + i * 16 + g;
                float v0 = As[s][r0][k8 + t];
                float v1 = As[s][r0 + 8][k8 + t];
                float v2 = As[s][r0][k8 + 4 + t];
                float v3 = As[s][r0 + 8][k8 + 4 + t];
                if constexpr (HILO) {
                    split_tf32(v0, af[i][0], al[i][0]);
                    split_tf32(v1, af[i][1], al[i][1]);
                    split_tf32(v2, af[i][2], al[i][2]);
                    split_tf32(v3, af[i][3], al[i][3]);
                } else {
                    af[i][0] = f2tf32(v0); af[i][1] = f2tf32(v1);
                    af[i][2] = f2tf32(v2); af[i][3] = f2tf32(v3);
                }
            }
            #pragma unroll
            for (int j = 0; j < 4; j++) {
                int n0 = warpN + j * 8 + g;
                float u0, u1;
                if constexpr (BT) {
                    u0 = Bs[s][n0 * BSTRIDE + k8 + t];
                    u1 = Bs[s][n0 * BSTRIDE + k8 + 4 + t];
                } else {
                    u0 = Bs[s][(k8 + t) * BSTRIDE + n0];
                    u1 = Bs[s][(k8 + 4 + t) * BSTRIDE + n0];
                }
                if constexpr (HILO) {
                    split_tf32(u0, bf[j][0], bl[j][0]);
                    split_tf32(u1, bf[j][1], bl[j][1]);
                } else {
                    bf[j][0] = f2tf32(u0); bf[j][1] = f2tf32(u1);
                }
            }
            #pragma unroll
            for (int i = 0; i < 4; i++)
                #pragma unroll
                for (int j = 0; j < 4; j++) {
                    if constexpr (HILO) {
                        // lo terms first (accumulate small, then large)
                        mma_tf32(acc[i][j][0], acc[i][j][1], acc[i][j][2], acc[i][j][3],
                                 al[i][0], al[i][1], al[i][2], al[i][3],
                                 bf[j][0], bf[j][1]);
                        mma_tf32(acc[i][j][0], acc[i][j][1], acc[i][j][2], acc[i][j][3],
                                 af[i][0], af[i][1], af[i][2], af[i][3],
                                 bl[j][0], bl[j][1]);
                    }
                    mma_tf32(acc[i][j][0], acc[i][j][1], acc[i][j][2], acc[i][j][3],
                             af[i][0], af[i][1], af[i][2], af[i][3],
                             bf[j][0], bf[j][1]);
                }
        }
        __syncthreads();
    }

    // epilogue
    #pragma unroll
    for (int i = 0; i < 4; i++) {
        int r0 = rowBase + warpM + i * 16 + g;
        int r1 = r0 + 8;
        #pragma unroll
        for (int j = 0; j < 4; j++) {
            int c0 = colBase + warpN + j * 8 + t * 2;
            float b0v = 0.f, b1v = 0.f;
            if (bias && c0 < N)     b0v = bias[c0];
            if (bias && c0 + 1 < N) b1v = bias[c0 + 1];
            if (r0 < M) {
                if (c0 < N) {
                    float vv = acc[i][j][0] * scale + b0v;
                    if (RELU) vv = fmaxf(vv, 0.f);
                    Cm[(long)r0 * ldc + c0] = vv;
                }
                if (c0 + 1 < N) {
                    float vv = acc[i][j][1] * scale + b1v;
                    if (RELU) vv = fmaxf(vv, 0.f);
                    Cm[(long)r0 * ldc + c0 + 1] = vv;
                }
            }
            if (r1 < M) {
                if (c0 < N) {
                    float vv = acc[i][j][2] * scale + b0v;
                    if (RELU) vv = fmaxf(vv, 0.f);
                    Cm[(long)r1 * ldc + c0] = vv;
                }
                if (c0 + 1 < N) {
                    float vv = acc[i][j][3] * scale + b1v;
                    if (RELU) vv = fmaxf(vv, 0.f);
                    Cm[(long)r1 * ldc + c0 + 1] = vv;
                }
            }
        }
    }
}

// ---------------- online row softmax over SL (2 reads + 1 write) ----------------
__global__ void softmax_kernel(float* __restrict__ sc) {
    long row = blockIdx.x;
    float* r = sc + row * SL_;
    __shared__ float redm[256], reds[256];
    // pass 1: online max+sum
    float m = -FLT_MAX, s = 0.f;
    for (int i = threadIdx.x; i < SL_; i += 256) {
        float x = r[i];
        if (x > m) { s = s * __expf(m - x) + 1.f; m = x; }
        else       { s += __expf(x - m); }
    }
    redm[threadIdx.x] = m; reds[threadIdx.x] = s; __syncthreads();
    for (int o = 128; o; o >>= 1) {
        if (threadIdx.x < o) {
            float m2 = redm[threadIdx.x + o], s2 = reds[threadIdx.x + o];
            float m1 = redm[threadIdx.x],     s1 = reds[threadIdx.x];
            float mn = fmaxf(m1, m2);
            redm[threadIdx.x] = mn;
            reds[threadIdx.x] = s1 * __expf(m1 - mn) + s2 * __expf(m2 - mn);
        }
        __syncthreads();
    }
    m = redm[0];
    float inv = 1.0f / reds[0];
    // pass 2: write normalized
    for (int i = threadIdx.x; i < SL_; i += 256)
        r[i] = __expf(r[i] - m) * inv;
}

// ---------------- pred head ----------------
__global__ void pred_kernel(const float* __restrict__ h, const float* __restrict__ w_p2,
                            const float* __restrict__ b_p2, float* __restrict__ out) {
    int bn = blockIdx.x;
    int b = bn / NW_, nw = bn % NW_;
    const float* hr = h + (long)bn * C_;
    __shared__ float r0[256], r1[256];
    float s0 = 0.f, s1 = 0.f;
    for (int c = threadIdx.x; c < C_; c += 256) {
        float x = hr[c];
        s0 += x * w_p2[c];
        s1 += x * w_p2[C_ + c];
    }
    r0[threadIdx.x] = s0; r1[threadIdx.x] = s1; __syncthreads();
    for (int o = 128; o; o >>= 1) {
        if (threadIdx.x < o) { r0[threadIdx.x] += r0[threadIdx.x + o]; r1[threadIdx.x] += r1[threadIdx.x + o]; }
        __syncthreads();
    }
    if (threadIdx.x == 0) {
        out[((long)b * 2 + 0) * NW_ + nw] = r0[0] + b_p2[0];
        out[((long)b * 2 + 1) * NW_ + nw] = r1[0] + b_p2[1];
    }
}

// ---------------- segment max-pool ----------------
__global__ void maxpool_kernel(const float* __restrict__ ob, const int* __restrict__ vid_len,
                               float* __restrict__ flat) {
    int bs = blockIdx.x;
    int b = bs / S_, s = bs % S_;
    int Lb = vid_len[b] * K_;
    int start = (s * Lb) / S_;
    int end = ((s + 1) * Lb + S_ - 1) / S_;
    if (end > SL_) end = SL_;
    const float* base = ob + (long)b * SL_ * C_;
    for (int c = threadIdx.x; c < C_; c += 256) {
        float m = -FLT_MAX;
        for (int t = start; t < end; t++) m = fmaxf(m, base[(long)t * C_ + c]);
        flat[(long)b * C_ * S_ + c * S_ + s] = m;
    }
}

// ---------------- st/en heads ----------------
__global__ void head_kernel(const float* __restrict__ flat,
                            const float* __restrict__ w_st, const float* __restrict__ b_st,
                            const float* __restrict__ w_en, const float* __restrict__ b_en,
                            float* __restrict__ dout) {
    int id = blockIdx.x;
    int which = id & 1;
    int s = (id >> 1) % S_;
    int b = id / (2 * S_);
    const float* w = which ? w_en : w_st;
    const float* bias = which ? b_en : b_st;
    const float* f = flat + (long)b * C_ * S_;
    const float* wr = w + (long)s * C_ * S_;
    __shared__ float red[256];
    float sum = 0.f;
    for (int i = threadIdx.x; i < C_ * S_; i += 256) sum += f[i] * wr[i];
    red[threadIdx.x] = sum; __syncthreads();
    for (int o = 128; o; o >>= 1) {
        if (threadIdx.x < o) red[threadIdx.x] += red[threadIdx.x + o];
        __syncthreads();
    }
    if (threadIdx.x == 0)
        dout[B_ * 2 * NW_ + which * B_ * S_ + b * S_ + s] = red[0] + bias[s];
}

// ---------------- host-side dispatch ----------------
static void gemm_tf(bool bt, bool relu, bool hilo,
                    const float* A, int lda, const float* Bm, int ldb,
                    float* Cm, int ldc, int M, int N, int Kd,
                    const float* bias, float scale,
                    long sAo, long sAi, long sBo, long sBi, long sCo, long sCi,
                    int zdiv, int zcount) {
    dim3 grid((N + 127) / 128, (M + 127) / 128, zcount);
    if (hilo) {
        // only BT, no-relu variant needed with hilo
        gemm_tf32_kernel<true, false, true><<<grid, 256>>>(A, lda, Bm, ldb, Cm, ldc, M, N, Kd, bias, scale, sAo, sAi, sBo, sBi, sCo, sCi, zdiv);
    } else if (bt) {
        if (relu) gemm_tf32_kernel<true, true, false><<<grid, 256>>>(A, lda, Bm, ldb, Cm, ldc, M, N, Kd, bias, scale, sAo, sAi, sBo, sBi, sCo, sCi, zdiv);
        else      gemm_tf32_kernel<true, false, false><<<grid, 256>>>(A, lda, Bm, ldb, Cm, ldc, M, N, Kd, bias, scale, sAo, sAi, sBo, sBi, sCo, sCi, zdiv);
    } else {
        gemm_tf32_kernel<false, false, false><<<grid, 256>>>(A, lda, Bm, ldb, Cm, ldc, M, N, Kd, bias, scale, sAo, sAi, sBo, sBi, sCo, sCi, zdiv);
    }
}

extern "C" void kernel_launch(void* const* d_in, const int* in_sizes, int n_in,
                              void* d_out, int out_size) {
    (void)in_sizes; (void)n_in; (void)out_size;
    const float* vis   = (const float*)d_in[0];
    const float* qf    = (const float*)d_in[1];
    const int*   vlen  = (const int*)  d_in[2];
    const float* w_v1  = (const float*)d_in[3];  const float* b_v1 = (const float*)d_in[4];
    const float* w_v2  = (const float*)d_in[5];  const float* b_v2 = (const float*)d_in[6];
    const float* w_s1  = (const float*)d_in[7];  const float* b_s1 = (const float*)d_in[8];
    const float* w_s2  = (const float*)d_in[9];  const float* b_s2 = (const float*)d_in[10];
    const float* w_in  = (const float*)d_in[11]; const float* b_in = (const float*)d_in[12];
    const float* w_out = (const float*)d_in[13]; const float* b_out= (const float*)d_in[14];
    const float* w_p1  = (const float*)d_in[15]; const float* b_p1 = (const float*)d_in[16];
    const float* w_p2  = (const float*)d_in[17]; const float* b_p2 = (const float*)d_in[18];
    const float* w_st  = (const float*)d_in[19]; const float* b_st = (const float*)d_in[20];
    const float* w_en  = (const float*)d_in[21]; const float* b_en = (const float*)d_in[22];
    float* out = (float*)d_out;

    float *pv, *pq, *v, *e1, *e2, *avg, *qq, *kk, *Qm, *Km, *Vm, *sc, *ao, *ob, *hb, *fl;
    int *lab, *mod;
    cudaGetSymbolAddress((void**)&pv, g_pv);
    cudaGetSymbolAddress((void**)&pq, g_pq);
    cudaGetSymbolAddress((void**)&v,  g_v);
    cudaGetSymbolAddress((void**)&e1, g_e1);
    cudaGetSymbolAddress((void**)&e2, g_e2);
    cudaGetSymbolAddress((void**)&lab, g_lab);
    cudaGetSymbolAddress((void**)&mod, g_mod);
    cudaGetSymbolAddress((void**)&avg, g_avg);
    cudaGetSymbolAddress((void**)&qq, g_qq);
    cudaGetSymbolAddress((void**)&kk, g_kk);
    cudaGetSymbolAddress((void**)&Qm, g_Q);
    cudaGetSymbolAddress((void**)&Km, g_K);
    cudaGetSymbolAddress((void**)&Vm, g_V);
    cudaGetSymbolAddress((void**)&sc, g_sc);
    cudaGetSymbolAddress((void**)&ao, g_ao);
    cudaGetSymbolAddress((void**)&ob, g_ob);
    cudaGetSymbolAddress((void**)&hb, g_h);
    cudaGetSymbolAddress((void**)&fl, g_fl);

    // 1. positional encodings
    pe_add_kernel<<<B_ * T_, 256>>>(vis, pv, T_, C_);
    pe_add_kernel<<<B_ * LQ_, 256>>>(qf, pq, LQ_, QD_);

    // 2. v = pe(vis) @ w_v1^T + b_v1  — 3xTF32 (near-fp32; feeds argmax labels)
    gemm_tf(true, false, true, pv, C_, w_v1, C_, v, C_, B_ * T_, C_, C_, b_v1, 1.f,
            0,0,0,0,0,0, 1, 1);

    // 3. e1/e2 — 3xTF32 (e1 feeds argmax)
    gemm_tf(true, false, true, pq, QD_, w_s1, QD_, e1, C_, B_ * LQ_, C_, QD_, b_s1, 1.f,
            0,0,0,0,0,0, 1, 1);
    gemm_tf(true, false, true, pq, QD_, w_s2, QD_, e2, C_, B_ * LQ_, C_, QD_, b_s2, 1.f,
            0,0,0,0,0,0, 1, 1);

    // 4-5. labels, mode, window means
    sim_argmax_kernel<<<B_ * T_, 256>>>(v, e1, lab);
    mode_kernel<<<(B_ * NW_ * K_ + 255) / 256, 256>>>(lab, mod);
    avg_kernel<<<B_ * SL_, 256>>>(v, avg);

    // 6. qq = avg @ w_v2^T + b_v2  (tf32)
    gemm_tf(true, false, false, avg, C_, w_v2, C_, qq, C_, B_ * SL_, C_, C_, b_v2, 1.f,
            0,0,0,0,0,0, 1, 1);

    // 7. kk = e2[mode]
    gather_kernel<<<B_ * SL_, 256>>>(e2, mod, kk);

    // 8. QKV projections (tf32)
    gemm_tf(true, false, false, qq, C_, w_in,                 C_, Qm, C_, B_ * SL_, C_, C_, b_in,          1.f, 0,0,0,0,0,0, 1, 1);
    gemm_tf(true, false, false, kk, C_, w_in + (long)C_ * C_, C_, Km, C_, B_ * SL_, C_, C_, b_in + C_,     1.f, 0,0,0,0,0,0, 1, 1);
    gemm_tf(true, false, false, qq, C_, w_in + 2L * C_ * C_,  C_, Vm, C_, B_ * SL_, C_, C_, b_in + 2 * C_, 1.f, 0,0,0,0,0,0, 1, 1);

    // 9. scores = Q K^T / sqrt(HD), batched over (b,h)  (tf32)
    gemm_tf(true, false, false, Qm, C_, Km, C_, sc, SL_, SL_, SL_, HD_, nullptr, 0.0625f,
            (long)SL_ * C_, HD_, (long)SL_ * C_, HD_, (long)H_ * SL_ * SL_, (long)SL_ * SL_, H_, B_ * H_);

    // 10. softmax (online)
    softmax_kernel<<<B_ * H_ * SL_, 256>>>(sc);

    // 11. attn @ V (NN, tf32), batched over (b,h)
    gemm_tf(false, false, false, sc, SL_, Vm, C_, ao, C_, SL_, HD_, SL_, nullptr, 1.f,
            (long)H_ * SL_ * SL_, (long)SL_ * SL_, (long)SL_ * C_, HD_, (long)SL_ * C_, HD_, H_, B_ * H_);

    // 12. out projection (tf32)
    gemm_tf(true, false, false, ao, C_, w_out, C_, ob, C_, B_ * SL_, C_, C_, b_out, 1.f,
            0,0,0,0,0,0, 1, 1);

    // 13. mlp (tf32 + relu)
    gemm_tf(true, true, false, ob, K_ * C_, w_p1, K_ * C_, hb, C_, B_ * NW_, C_, K_ * C_, b_p1, 1.f,
            0,0,0,0,0,0, 1, 1);

    // 14-15. heads
    pred_kernel<<<B_ * NW_, 256>>>(hb, w_p2, b_p2, out);
    maxpool_kernel<<<B_ * S_, 256>>>(ob, vlen, fl);
    head_kernel<<<B_ * S_ * 2, 256>>>(fl, w_st, b_st, w_en, b_en, out);
}

// round 17
// speedup vs baseline: 3.2943x; 1.0515x over previous
#include <cuda_runtime.h>
#include <math.h>
#include <float.h>
#include <stdint.h>

// ---------------- problem constants ----------------
constexpr int B_  = 8;
constexpr int T_  = 256;
constexpr int C_  = 1024;
constexpr int QD_ = 768;
constexpr int LQ_ = 24;
constexpr int K_  = 4;
constexpr int CC_ = 4;     // W/K
constexpr int NW_ = 241;   // T - W + 1
constexpr int S_  = 8;
constexpr int H_  = 4;
constexpr int HD_ = 256;   // C/H
constexpr int SL_ = NW_ * K_;  // 964
constexpr int C2_ = 2 * C_;    // merged e1|e2 width

// ---------------- scratch (static device globals; no allocations) ----------------
__device__ float g_pv [B_*T_*C_];
__device__ float g_pq [B_*LQ_*QD_];
__device__ float g_v  [B_*T_*C_];
__device__ float g_ws [C2_*QD_];           // concat [w_s1; w_s2]
__device__ float g_bs [C2_];               // concat [b_s1; b_s2]
__device__ float g_e12[B_*LQ_*C2_];        // [e1 | e2] combined output
__device__ int   g_lab[B_*T_];
__device__ int   g_mod[B_*NW_*K_];
__device__ float g_avg[B_*SL_*C_];
__device__ float g_qq [B_*SL_*C_];
__device__ float g_kk [B_*SL_*C_];
__device__ float g_Q  [B_*SL_*C_];
__device__ float g_K  [B_*SL_*C_];
__device__ float g_V  [B_*SL_*C_];
__device__ float g_sc [(long)B_*H_*SL_*SL_];
__device__ float g_ao [B_*SL_*C_];
__device__ float g_ob [B_*SL_*C_];
__device__ float g_h  [B_*NW_*C_];
__device__ float g_fl [B_*C_*S_];

// ---------------- positional encoding add ----------------
__global__ void pe_add_kernel(const float* __restrict__ x, float* __restrict__ y,
                              int L, int d) {
    int row = blockIdx.x;
    int l = row % L;
    const float* xr = x + (long)row * d;
    float* yr = y + (long)row * d;
    float pos = (float)l;
    float c0 = logf(10000.0f) / (float)d;
    for (int c = threadIdx.x; c < d; c += blockDim.x) {
        int i = c >> 1;
        float freq = expf(-(float)(2 * i) * c0);
        float ang = pos * freq;
        float pe = (c & 1) ? cosf(ang) : sinf(ang);
        yr[c] = xr[c] + pe;
    }
}

// ---------------- concat [w_s1;w_s2] and [b_s1;b_s2] into scratch ----------------
__global__ void concat_ws_kernel(const float* __restrict__ w1, const float* __restrict__ w2,
                                 const float* __restrict__ b1, const float* __restrict__ b2,
                                 float* __restrict__ w, float* __restrict__ b) {
    long n = (long)C_ * QD_;
    long i = (long)blockIdx.x * 256 + threadIdx.x;
    if (i < n)           w[i] = w1[i];
    else if (i < 2 * n)  w[i] = w2[i - n];
    if (i < C_)          b[i] = b1[i];
    else if (i < C2_)    b[i] = b2[i - C_];
}

// ---------------- sim = v . e1^T, fused argmax over LQ ----------------
// e1 rows live at stride C2_ inside g_e12 (columns [0, C_)).
__global__ void sim_argmax_kernel(const float* __restrict__ v,
                                  const float* __restrict__ e12,
                                  int* __restrict__ labels) {
    int bt = blockIdx.x;
    int b = bt / T_;
    __shared__ float sv[C_];
    __shared__ float svals[LQ_];
    const float* vr = v + (long)bt * C_;
    for (int c = threadIdx.x; c < C_; c += 256) sv[c] = vr[c];
    __syncthreads();
    int warp = threadIdx.x >> 5, lane = threadIdx.x & 31;
    for (int l = warp; l < LQ_; l += 8) {
        const float* er = e12 + ((long)b * LQ_ + l) * C2_;
        float s = 0.f;
        for (int c = lane; c < C_; c += 32) s += sv[c] * er[c];
        #pragma unroll
        for (int o = 16; o; o >>= 1) s += __shfl_xor_sync(0xffffffffu, s, o);
        if (lane == 0) svals[l] = s;
    }
    __syncthreads();
    if (threadIdx.x == 0) {
        float best = svals[0]; int bi = 0;
        for (int l = 1; l < LQ_; l++)
            if (svals[l] > best) { best = svals[l]; bi = l; }
        labels[bt] = bi;
    }
}

// ---------------- majority vote (mode) per chunk ----------------
__global__ void mode_kernel(const int* __restrict__ labels, int* __restrict__ mode) {
    int idx = blockIdx.x * blockDim.x + threadIdx.x;
    if (idx >= B_ * NW_ * K_) return;
    int k = idx % K_;
    int nw = (idx / K_) % NW_;
    int b = idx / (K_ * NW_);
    int la[CC_];
    #pragma unroll
    for (int cc = 0; cc < CC_; cc++) la[cc] = labels[b * T_ + nw + k * CC_ + cc];
    int bestLab = 0x7fffffff, bestCnt = 0;
    #pragma unroll
    for (int cc = 0; cc < CC_; cc++) {
        int v = la[cc], cnt = 0;
        #pragma unroll
        for (int j = 0; j < CC_; j++) cnt += (la[j] == v) ? 1 : 0;
        if (cnt > bestCnt || (cnt == bestCnt && v < bestLab)) { bestCnt = cnt; bestLab = v; }
    }
    mode[idx] = bestLab;
}

// ---------------- window chunk mean over CC rows ----------------
__global__ void avg_kernel(const float* __restrict__ v, float* __restrict__ avg) {
    int s = blockIdx.x % SL_;
    int b = blockIdx.x / SL_;
    int nw = s / K_, k = s % K_;
    const float* base = v + ((long)b * T_ + nw + k * CC_) * C_;
    float* o = avg + ((long)b * SL_ + s) * C_;
    for (int c = threadIdx.x; c < C_; c += 256)
        o[c] = 0.25f * (base[c] + base[C_ + c] + base[2 * C_ + c] + base[3 * C_ + c]);
}

// ---------------- gather e2 rows by mode ----------------
// e2 rows live at stride C2_ inside g_e12 (columns [C_, 2C_)).
__global__ void gather_kernel(const float* __restrict__ e12, const int* __restrict__ mode,
                              float* __restrict__ kk) {
    int s = blockIdx.x % SL_;
    int b = blockIdx.x / SL_;
    int m = mode[b * NW_ * K_ + s];
    const float* src = e12 + ((long)b * LQ_ + m) * C2_ + C_;
    float* dst = kk + ((long)b * SL_ + s) * C_;
    for (int c = threadIdx.x; c < C_; c += 256) dst[c] = src[c];
}

// ================= tf32 tensor-core GEMM =================
// C = scale * (A @ op(B)) [+bias][relu]
// BT=true:  B is (N,Kd) row-major (x @ W^T style).
// BT=false: B is (Kd,N) row-major.
// HILO=true: 3xTF32 error-compensated (near-fp32 accuracy: hi*hi + hi*lo + lo*hi).
// 128x128 CTA tile, BK=16, cp.async double buffer, 8 warps at 64x32 warp tiles.

__device__ __forceinline__ uint32_t f2tf32(float x) {
    uint32_t u;
    asm("cvt.rna.tf32.f32 %0, %1;" : "=r"(u) : "f"(x));
    return u;
}
__device__ __forceinline__ void split_tf32(float x, uint32_t& hi, uint32_t& lo) {
    asm("cvt.rna.tf32.f32 %0, %1;" : "=r"(hi) : "f"(x));
    float r = x - __uint_as_float(hi);
    asm("cvt.rna.tf32.f32 %0, %1;" : "=r"(lo) : "f"(r));
}
__device__ __forceinline__ void cp_async16(uint32_t saddr, const void* gptr, int srcBytes) {
    asm volatile("cp.async.cg.shared.global [%0], [%1], 16, %2;\n"
                 :: "r"(saddr), "l"(gptr), "r"(srcBytes));
}
__device__ __forceinline__ void cp_commit() {
    asm volatile("cp.async.commit_group;\n");
}
template<int N>
__device__ __forceinline__ void cp_wait() {
    asm volatile("cp.async.wait_group %0;\n" :: "n"(N));
}
__device__ __forceinline__ void mma_tf32(float& d0, float& d1, float& d2, float& d3,
                                         uint32_t a0, uint32_t a1, uint32_t a2, uint32_t a3,
                                         uint32_t b0, uint32_t b1) {
    asm volatile("mma.sync.aligned.m16n8k8.row.col.f32.tf32.tf32.f32 "
                 "{%0,%1,%2,%3}, {%4,%5,%6,%7}, {%8,%9}, {%0,%1,%2,%3};\n"
                 : "+f"(d0), "+f"(d1), "+f"(d2), "+f"(d3)
                 : "r"(a0), "r"(a1), "r"(a2), "r"(a3), "r"(b0), "r"(b1));
}

template<bool BT, bool RELU, bool HILO>
__global__ __launch_bounds__(256) void gemm_tf32_kernel(
    const float* __restrict__ A, int lda,
    const float* __restrict__ Bm, int ldb,
    float* __restrict__ Cm, int ldc,
    int M, int N, int Kd,
    const float* __restrict__ bias, float scale,
    long sAo, long sAi, long sBo, long sBi, long sCo, long sCi, int zdiv)
{
    constexpr int BK = 16;
    constexpr int APAD = 20;                       // A row stride (floats)
    constexpr int BSTRIDE = BT ? 20 : 132;         // BT: [n][k] stride 20; NN: [k][n] stride 132
    constexpr int BSZ = BT ? 128 * 20 : BK * 132;

    __shared__ float As[2][128][APAD];
    __shared__ float Bs[2][BSZ];

    int z = blockIdx.z;
    int zo = z / zdiv, zi = z - zo * zdiv;
    A  += zo * sAo + zi * sAi;
    Bm += zo * sBo + zi * sBi;
    Cm += zo * sCo + zi * sCi;

    int tid = threadIdx.x;
    int wid = tid >> 5, lane = tid & 31;
    int g = lane >> 2, t = lane & 3;
    int warpM = (wid >> 2) * 64;   // 2 warps in M
    int warpN = (wid & 3) * 32;    // 4 warps in N
    int rowBase = blockIdx.y * 128;
    int colBase = blockIdx.x * 128;

    float acc[4][4][4];
    #pragma unroll
    for (int i = 0; i < 4; i++)
        #pragma unroll
        for (int j = 0; j < 4; j++)
            #pragma unroll
            for (int q = 0; q < 4; q++) acc[i][j][q] = 0.f;

    int KT = (Kd + BK - 1) / BK;

    auto load_stage = [&](int kt, int s) {
        int k0 = kt * BK;
        #pragma unroll
        for (int i = 0; i < 2; i++) {
            int v = i * 256 + tid;
            int r = v >> 2, kv = (v & 3) * 4;
            int gr = rowBase + r, gk = k0 + kv;
            bool ok = (gr < M) && (gk < Kd);
            long gro = ok ? (long)gr : 0;
            long gko = ok ? (long)gk : 0;
            uint32_t sa = (uint32_t)__cvta_generic_to_shared(&As[s][r][kv]);
            cp_async16(sa, A + gro * lda + gko, ok ? 16 : 0);
        }
        #pragma unroll
        for (int i = 0; i < 2; i++) {
            int v = i * 256 + tid;
            if constexpr (BT) {
                int n = v >> 2, kv = (v & 3) * 4;
                int gn = colBase + n, gk = k0 + kv;
                bool ok = (gn < N) && (gk < Kd);
                long gno = ok ? (long)gn : 0;
                long gko = ok ? (long)gk : 0;
                uint32_t sa = (uint32_t)__cvta_generic_to_shared(&Bs[s][n * BSTRIDE + kv]);
                cp_async16(sa, Bm + gno * ldb + gko, ok ? 16 : 0);
            } else {
                int kk = v >> 5, nv = (v & 31) * 4;
                int gk = k0 + kk, gn = colBase + nv;
                bool ok = (gk < Kd) && (gn < N);
                long gko = ok ? (long)gk : 0;
                long gno = ok ? (long)gn : 0;
                uint32_t sa = (uint32_t)__cvta_generic_to_shared(&Bs[s][kk * BSTRIDE + nv]);
                cp_async16(sa, Bm + gko * ldb + gno, ok ? 16 : 0);
            }
        }
    };

    load_stage(0, 0);
    cp_commit();

    for (int kt = 0; kt < KT; kt++) {
        int s = kt & 1;
        if (kt + 1 < KT) load_stage(kt + 1, (kt + 1) & 1);
        cp_commit();
        cp_wait<1>();
        __syncthreads();

        #pragma unroll
        for (int ks = 0; ks < 2; ks++) {
            int k8 = ks * 8;
            uint32_t af[4][4], bf[4][2];
            uint32_t al[4][4], bl[4][2];
            #pragma unroll
            for (int i = 0; i < 4; i++) {
                int r0 = warpM + i * 16 + g;
                float v0 = As[s][r0][k8 + t];
                float v1 = As[s][r0 + 8][k8 + t];
                float v2 = As[s][r0][k8 + 4 + t];
                float v3 = As[s][r0 + 8][k8 + 4 + t];
                if constexpr (HILO) {
                    split_tf32(v0, af[i][0], al[i][0]);
                    split_tf32(v1, af[i][1], al[i][1]);
                    split_tf32(v2, af[i][2], al[i][2]);
                    split_tf32(v3, af[i][3], al[i][3]);
                } else {
                    af[i][0] = f2tf32(v0); af[i][1] = f2tf32(v1);
                    af[i][2] = f2tf32(v2); af[i][3] = f2tf32(v3);
                }
            }
            #pragma unroll
            for (int j = 0; j < 4; j++) {
                int n0 = warpN + j * 8 + g;
                float u0, u1;
                if constexpr (BT) {
                    u0 = Bs[s][n0 * BSTRIDE + k8 + t];
                    u1 = Bs[s][n0 * BSTRIDE + k8 + 4 + t];
                } else {
                    u0 = Bs[s][(k8 + t) * BSTRIDE + n0];
                    u1 = Bs[s][(k8 + 4 + t) * BSTRIDE + n0];
                }
                if constexpr (HILO) {
                    split_tf32(u0, bf[j][0], bl[j][0]);
                    split_tf32(u1, bf[j][1], bl[j][1]);
                } else {
                    bf[j][0] = f2tf32(u0); bf[j][1] = f2tf32(u1);
                }
            }
            #pragma unroll
            for (int i = 0; i < 4; i++)
                #pragma unroll
                for (int j = 0; j < 4; j++) {
                    if constexpr (HILO) {
                        // lo terms first (accumulate small, then large)
                        mma_tf32(acc[i][j][0], acc[i][j][1], acc[i][j][2], acc[i][j][3],
                                 al[i][0], al[i][1], al[i][2], al[i][3],
                                 bf[j][0], bf[j][1]);
                        mma_tf32(acc[i][j][0], acc[i][j][1], acc[i][j][2], acc[i][j][3],
                                 af[i][0], af[i][1], af[i][2], af[i][3],
                                 bl[j][0], bl[j][1]);
                    }
                    mma_tf32(acc[i][j][0], acc[i][j][1], acc[i][j][2], acc[i][j][3],
                             af[i][0], af[i][1], af[i][2], af[i][3],
                             bf[j][0], bf[j][1]);
                }
        }
        __syncthreads();
    }

    // epilogue
    #pragma unroll
    for (int i = 0; i < 4; i++) {
        int r0 = rowBase + warpM + i * 16 + g;
        int r1 = r0 + 8;
        #pragma unroll
        for (int j = 0; j < 4; j++) {
            int c0 = colBase + warpN + j * 8 + t * 2;
            float b0v = 0.f, b1v = 0.f;
            if (bias && c0 < N)     b0v = bias[c0];
            if (bias && c0 + 1 < N) b1v = bias[c0 + 1];
            if (r0 < M) {
                if (c0 < N) {
                    float vv = acc[i][j][0] * scale + b0v;
                    if (RELU) vv = fmaxf(vv, 0.f);
                    Cm[(long)r0 * ldc + c0] = vv;
                }
                if (c0 + 1 < N) {
                    float vv = acc[i][j][1] * scale + b1v;
                    if (RELU) vv = fmaxf(vv, 0.f);
                    Cm[(long)r0 * ldc + c0 + 1] = vv;
                }
            }
            if (r1 < M) {
                if (c0 < N) {
                    float vv = acc[i][j][2] * scale + b0v;
                    if (RELU) vv = fmaxf(vv, 0.f);
                    Cm[(long)r1 * ldc + c0] = vv;
                }
                if (c0 + 1 < N) {
                    float vv = acc[i][j][3] * scale + b1v;
                    if (RELU) vv = fmaxf(vv, 0.f);
                    Cm[(long)r1 * ldc + c0 + 1] = vv;
                }
            }
        }
    }
}

// ---------------- online row softmax over SL (2 reads + 1 write) ----------------
__global__ void softmax_kernel(float* __restrict__ sc) {
    long row = blockIdx.x;
    float* r = sc + row * SL_;
    __shared__ float redm[256], reds[256];
    // pass 1: online max+sum
    float m = -FLT_MAX, s = 0.f;
    for (int i = threadIdx.x; i < SL_; i += 256) {
        float x = r[i];
        if (x > m) { s = s * __expf(m - x) + 1.f; m = x; }
        else       { s += __expf(x - m); }
    }
    redm[threadIdx.x] = m; reds[threadIdx.x] = s; __syncthreads();
    for (int o = 128; o; o >>= 1) {
        if (threadIdx.x < o) {
            float m2 = redm[threadIdx.x + o], s2 = reds[threadIdx.x + o];
            float m1 = redm[threadIdx.x],     s1 = reds[threadIdx.x];
            float mn = fmaxf(m1, m2);
            redm[threadIdx.x] = mn;
            reds[threadIdx.x] = s1 * __expf(m1 - mn) + s2 * __expf(m2 - mn);
        }
        __syncthreads();
    }
    m = redm[0];
    float inv = 1.0f / reds[0];
    // pass 2: write normalized
    for (int i = threadIdx.x; i < SL_; i += 256)
        r[i] = __expf(r[i] - m) * inv;
}

// ---------------- pred head ----------------
__global__ void pred_kernel(const float* __restrict__ h, const float* __restrict__ w_p2,
                            const float* __restrict__ b_p2, float* __restrict__ out) {
    int bn = blockIdx.x;
    int b = bn / NW_, nw = bn % NW_;
    const float* hr = h + (long)bn * C_;
    __shared__ float r0[256], r1[256];
    float s0 = 0.f, s1 = 0.f;
    for (int c = threadIdx.x; c < C_; c += 256) {
        float x = hr[c];
        s0 += x * w_p2[c];
        s1 += x * w_p2[C_ + c];
    }
    r0[threadIdx.x] = s0; r1[threadIdx.x] = s1; __syncthreads();
    for (int o = 128; o; o >>= 1) {
        if (threadIdx.x < o) { r0[threadIdx.x] += r0[threadIdx.x + o]; r1[threadIdx.x] += r1[threadIdx.x + o]; }
        __syncthreads();
    }
    if (threadIdx.x == 0) {
        out[((long)b * 2 + 0) * NW_ + nw] = r0[0] + b_p2[0];
        out[((long)b * 2 + 1) * NW_ + nw] = r1[0] + b_p2[1];
    }
}

// ---------------- segment max-pool ----------------
__global__ void maxpool_kernel(const float* __restrict__ ob, const int* __restrict__ vid_len,
                               float* __restrict__ flat) {
    int bs = blockIdx.x;
    int b = bs / S_, s = bs % S_;
    int Lb = vid_len[b] * K_;
    int start = (s * Lb) / S_;
    int end = ((s + 1) * Lb + S_ - 1) / S_;
    if (end > SL_) end = SL_;
    const float* base = ob + (long)b * SL_ * C_;
    for (int c = threadIdx.x; c < C_; c += 256) {
        float m = -FLT_MAX;
        for (int t = start; t < end; t++) m = fmaxf(m, base[(long)t * C_ + c]);
        flat[(long)b * C_ * S_ + c * S_ + s] = m;
    }
}

// ---------------- st/en heads ----------------
__global__ void head_kernel(const float* __restrict__ flat,
                            const float* __restrict__ w_st, const float* __restrict__ b_st,
                            const float* __restrict__ w_en, const float* __restrict__ b_en,
                            float* __restrict__ dout) {
    int id = blockIdx.x;
    int which = id & 1;
    int s = (id >> 1) % S_;
    int b = id / (2 * S_);
    const float* w = which ? w_en : w_st;
    const float* bias = which ? b_en : b_st;
    const float* f = flat + (long)b * C_ * S_;
    const float* wr = w + (long)s * C_ * S_;
    __shared__ float red[256];
    float sum = 0.f;
    for (int i = threadIdx.x; i < C_ * S_; i += 256) sum += f[i] * wr[i];
    red[threadIdx.x] = sum; __syncthreads();
    for (int o = 128; o; o >>= 1) {
        if (threadIdx.x < o) red[threadIdx.x] += red[threadIdx.x + o];
        __syncthreads();
    }
    if (threadIdx.x == 0)
        dout[B_ * 2 * NW_ + which * B_ * S_ + b * S_ + s] = red[0] + bias[s];
}

// ---------------- host-side dispatch ----------------
static void gemm_tf(bool bt, bool relu, bool hilo,
                    const float* A, int lda, const float* Bm, int ldb,
                    float* Cm, int ldc, int M, int N, int Kd,
                    const float* bias, float scale,
                    long sAo, long sAi, long sBo, long sBi, long sCo, long sCi,
                    int zdiv, int zcount) {
    dim3 grid((N + 127) / 128, (M + 127) / 128, zcount);
    if (hilo) {
        // only BT, no-relu variant needed with hilo
        gemm_tf32_kernel<true, false, true><<<grid, 256>>>(A, lda, Bm, ldb, Cm, ldc, M, N, Kd, bias, scale, sAo, sAi, sBo, sBi, sCo, sCi, zdiv);
    } else if (bt) {
        if (relu) gemm_tf32_kernel<true, true, false><<<grid, 256>>>(A, lda, Bm, ldb, Cm, ldc, M, N, Kd, bias, scale, sAo, sAi, sBo, sBi, sCo, sCi, zdiv);
        else      gemm_tf32_kernel<true, false, false><<<grid, 256>>>(A, lda, Bm, ldb, Cm, ldc, M, N, Kd, bias, scale, sAo, sAi, sBo, sBi, sCo, sCi, zdiv);
    } else {
        gemm_tf32_kernel<false, false, false><<<grid, 256>>>(A, lda, Bm, ldb, Cm, ldc, M, N, Kd, bias, scale, sAo, sAi, sBo, sBi, sCo, sCi, zdiv);
    }
}

extern "C" void kernel_launch(void* const* d_in, const int* in_sizes, int n_in,
                              void* d_out, int out_size) {
    (void)in_sizes; (void)n_in; (void)out_size;
    const float* vis   = (const float*)d_in[0];
    const float* qf    = (const float*)d_in[1];
    const int*   vlen  = (const int*)  d_in[2];
    const float* w_v1  = (const float*)d_in[3];  const float* b_v1 = (const float*)d_in[4];
    const float* w_v2  = (const float*)d_in[5];  const float* b_v2 = (const float*)d_in[6];
    const float* w_s1  = (const float*)d_in[7];  const float* b_s1 = (const float*)d_in[8];
    const float* w_s2  = (const float*)d_in[9];  const float* b_s2 = (const float*)d_in[10];
    const float* w_in  = (const float*)d_in[11]; const float* b_in = (const float*)d_in[12];
    const float* w_out = (const float*)d_in[13]; const float* b_out= (const float*)d_in[14];
    const float* w_p1  = (const float*)d_in[15]; const float* b_p1 = (const float*)d_in[16];
    const float* w_p2  = (const float*)d_in[17]; const float* b_p2 = (const float*)d_in[18];
    const float* w_st  = (const float*)d_in[19]; const float* b_st = (const float*)d_in[20];
    const float* w_en  = (const float*)d_in[21]; const float* b_en = (const float*)d_in[22];
    float* out = (float*)d_out;

    float *pv, *pq, *v, *ws, *bs, *e12, *avg, *qq, *kk, *Qm, *Km, *Vm, *sc, *ao, *ob, *hb, *fl;
    int *lab, *mod;
    cudaGetSymbolAddress((void**)&pv, g_pv);
    cudaGetSymbolAddress((void**)&pq, g_pq);
    cudaGetSymbolAddress((void**)&v,  g_v);
    cudaGetSymbolAddress((void**)&ws, g_ws);
    cudaGetSymbolAddress((void**)&bs, g_bs);
    cudaGetSymbolAddress((void**)&e12, g_e12);
    cudaGetSymbolAddress((void**)&lab, g_lab);
    cudaGetSymbolAddress((void**)&mod, g_mod);
    cudaGetSymbolAddress((void**)&avg, g_avg);
    cudaGetSymbolAddress((void**)&qq, g_qq);
    cudaGetSymbolAddress((void**)&kk, g_kk);
    cudaGetSymbolAddress((void**)&Qm, g_Q);
    cudaGetSymbolAddress((void**)&Km, g_K);
    cudaGetSymbolAddress((void**)&Vm, g_V);
    cudaGetSymbolAddress((void**)&sc, g_sc);
    cudaGetSymbolAddress((void**)&ao, g_ao);
    cudaGetSymbolAddress((void**)&ob, g_ob);
    cudaGetSymbolAddress((void**)&hb, g_h);
    cudaGetSymbolAddress((void**)&fl, g_fl);

    // 1. positional encodings + weight concat (independent prep work)
    pe_add_kernel<<<B_ * T_, 256>>>(vis, pv, T_, C_);
    pe_add_kernel<<<B_ * LQ_, 256>>>(qf, pq, LQ_, QD_);
    {
        long n2 = 2L * C_ * QD_;
        concat_ws_kernel<<<(int)((n2 + 255) / 256), 256>>>(w_s1, w_s2, b_s1, b_s2, ws, bs);
    }

    // 2. v = pe(vis) @ w_v1^T + b_v1  — 3xTF32 (near-fp32; feeds argmax labels)
    gemm_tf(true, false, true, pv, C_, w_v1, C_, v, C_, B_ * T_, C_, C_, b_v1, 1.f,
            0,0,0,0,0,0, 1, 1);

    // 3. [e1|e2] = pe(q) @ [w_s1;w_s2]^T — single merged 3xTF32 GEMM (M=192, N=2048)
    gemm_tf(true, false, true, pq, QD_, ws, QD_, e12, C2_, B_ * LQ_, C2_, QD_, bs, 1.f,
            0,0,0,0,0,0, 1, 1);

    // 4-5. labels, mode, window means
    sim_argmax_kernel<<<B_ * T_, 256>>>(v, e12, lab);
    mode_kernel<<<(B_ * NW_ * K_ + 255) / 256, 256>>>(lab, mod);
    avg_kernel<<<B_ * SL_, 256>>>(v, avg);

    // 6. qq = avg @ w_v2^T + b_v2  (tf32)
    gemm_tf(true, false, false, avg, C_, w_v2, C_, qq, C_, B_ * SL_, C_, C_, b_v2, 1.f,
            0,0,0,0,0,0, 1, 1);

    // 7. kk = e2[mode]  (e2 = columns [C_, 2C_) of e12)
    gather_kernel<<<B_ * SL_, 256>>>(e12, mod, kk);

    // 8. QKV projections (tf32)
    gemm_tf(true, false, false, qq, C_, w_in,                 C_, Qm, C_, B_ * SL_, C_, C_, b_in,          1.f, 0,0,0,0,0,0, 1, 1);
    gemm_tf(true, false, false, kk, C_, w_in + (long)C_ * C_, C_, Km, C_, B_ * SL_, C_, C_, b_in + C_,     1.f, 0,0,0,0,0,0, 1, 1);
    gemm_tf(true, false, false, qq, C_, w_in + 2L * C_ * C_,  C_, Vm, C_, B_ * SL_, C_, C_, b_in + 2 * C_, 1.f, 0,0,0,0,0,0, 1, 1);

    // 9. scores = Q K^T / sqrt(HD), batched over (b,h)  (tf32)
    gemm_tf(true, false, false, Qm, C_, Km, C_, sc, SL_, SL_, SL_, HD_, nullptr, 0.0625f,
            (long)SL_ * C_, HD_, (long)SL_ * C_, HD_, (long)H_ * SL_ * SL_, (long)SL_ * SL_, H_, B_ * H_);

    // 10. softmax (online)
    softmax_kernel<<<B_ * H_ * SL_, 256>>>(sc);

    // 11. attn @ V (NN, tf32), batched over (b,h)
    gemm_tf(false, false, false, sc, SL_, Vm, C_, ao, C_, SL_, HD_, SL_, nullptr, 1.f,
            (long)H_ * SL_ * SL_, (long)SL_ * SL_, (long)SL_ * C_, HD_, (long)SL_ * C_, HD_, H_, B_ * H_);

    // 12. out projection (tf32)
    gemm_tf(true, false, false, ao, C_, w_out, C_, ob, C_, B_ * SL_, C_, C_, b_out, 1.f,
            0,0,0,0,0,0, 1, 1);

    // 13. mlp (tf32 + relu)
    gemm_tf(true, true, false, ob, K_ * C_, w_p1, K_ * C_, hb, C_, B_ * NW_, C_, K_ * C_, b_p1, 1.f,
            0,0,0,0,0,0, 1, 1);

    // 14-15. heads
    pred_kernel<<<B_ * NW_, 256>>>(hb, w_p2, b_p2, out);
    maxpool_kernel<<<B_ * S_, 256>>>(ob, vlen, fl);
    head_kernel<<<B_ * S_ * 2, 256>>>(fl, w_st, b_st, w_en, b_en, out);
}